// round 4
// baseline (speedup 1.0000x reference)
#include <cuda_runtime.h>
#include <math.h>

// Problem constants
#define BB 4
#define SS 2048
#define DD 1024
#define HH 16
#define DKK 64
#define MS (BB*SS)          // 8192 rows

// Scratch (static device arrays — no allocation at runtime)
__device__ float g_Q[MS*DD];
__device__ float g_K[MS*DD];
__device__ float g_V[MS*DD];
__device__ float g_AO[MS*DD];

// ---------------------------------------------------------------------------
// GEMM: C[M,N] = A[M,K] * W[N,K]^T     (fp32, 64x64 tile, BK=16, 256 threads)
// ---------------------------------------------------------------------------
__global__ __launch_bounds__(256)
void gemm_abt_kernel(const float* __restrict__ A,
                     const float* __restrict__ W,
                     float* __restrict__ C,
                     int M, int N, int K) {
    __shared__ float As[64][17];
    __shared__ float Ws[64][17];

    const int tid = threadIdx.x;
    const int tx = tid & 15;        // 0..15
    const int ty = tid >> 4;        // 0..15
    const int row0 = blockIdx.y * 64;
    const int col0 = blockIdx.x * 64;

    const int lr = tid >> 2;        // 0..63  (load row)
    const int lc = (tid & 3) * 4;   // 0,4,8,12 (load col, float4)

    float acc[4][4] = {};

    for (int k0 = 0; k0 < K; k0 += 16) {
        float4 av = *reinterpret_cast<const float4*>(&A[(long)(row0 + lr) * K + k0 + lc]);
        float4 wv = *reinterpret_cast<const float4*>(&W[(long)(col0 + lr) * K + k0 + lc]);
        __syncthreads();
        As[lr][lc + 0] = av.x; As[lr][lc + 1] = av.y;
        As[lr][lc + 2] = av.z; As[lr][lc + 3] = av.w;
        Ws[lr][lc + 0] = wv.x; Ws[lr][lc + 1] = wv.y;
        Ws[lr][lc + 2] = wv.z; Ws[lr][lc + 3] = wv.w;
        __syncthreads();

        #pragma unroll
        for (int kk = 0; kk < 16; kk++) {
            float a[4], w[4];
            #pragma unroll
            for (int i = 0; i < 4; i++) a[i] = As[ty * 4 + i][kk];
            #pragma unroll
            for (int j = 0; j < 4; j++) w[j] = Ws[tx * 4 + j][kk];
            #pragma unroll
            for (int i = 0; i < 4; i++)
                #pragma unroll
                for (int j = 0; j < 4; j++)
                    acc[i][j] += a[i] * w[j];
        }
    }

    #pragma unroll
    for (int i = 0; i < 4; i++) {
        #pragma unroll
        for (int j = 0; j < 4; j++) {
            C[(long)(row0 + ty * 4 + i) * N + col0 + tx * 4 + j] = acc[i][j];
        }
    }
}

// ---------------------------------------------------------------------------
// RoPE applied in-place to Q and K.
// Layout: [B, S, H, DK]. Pairs (2i, 2i+1) within each head's 64 dims.
// inv_freq = theta^(-2i/64) ; ang = pos * inv_freq
// ---------------------------------------------------------------------------
__global__ void rope_kernel(float* __restrict__ Q, float* __restrict__ K,
                            const int* __restrict__ pos) {
    const int idx = blockIdx.x * blockDim.x + threadIdx.x;
    // total pairs = MS * DD / 2 = B*S*H*32
    const int i  = idx & 31;           // pair index within head, 0..31
    const int h  = (idx >> 5) & (HH - 1);
    const int bs = idx >> 9;           // b*S + s  (32*16 = 512 = 2^9)
    const int s  = bs & (SS - 1);

    const float p = (float)pos[s];
    // inv_freq = 2^( -(2i/64) * log2(theta) ) ; log2(10000)/32 = 0.41524101186...
    const float inv = exp2f(-(float)i * 0.4152410118607953f);
    const float ang = p * inv;
    float sn, cs;
    sincosf(ang, &sn, &cs);

    const long base = (long)bs * DD + h * DKK + 2 * i;

    float q1 = Q[base], q2 = Q[base + 1];
    Q[base]     = q1 * cs - q2 * sn;
    Q[base + 1] = q1 * sn + q2 * cs;

    float k1 = K[base], k2 = K[base + 1];
    K[base]     = k1 * cs - k2 * sn;
    K[base + 1] = k1 * sn + k2 * cs;
}

// ---------------------------------------------------------------------------
// Causal flash attention, fp32. One thread per query row.
// Grid: (S/128, B*H), block 128 threads.
// Q/K/V layout: [B, S, H*DK]; output written to [B, S, H*DK].
// ---------------------------------------------------------------------------
__global__ __launch_bounds__(128)
void attn_kernel(const float* __restrict__ Q,
                 const float* __restrict__ K,
                 const float* __restrict__ V,
                 float* __restrict__ O) {
    constexpr int RT = 128;   // query rows per block (= blockDim.x)
    constexpr int TK = 64;    // key tile rows

    __shared__ float Ks[TK][DKK];
    __shared__ float Vs[TK][DKK];

    const int tid = threadIdx.x;
    const int bh  = blockIdx.y;
    const int b   = bh >> 4;          // / HH
    const int h   = bh & (HH - 1);
    const int sq  = blockIdx.x * RT + tid;

    const float* qptr = Q + ((long)(b * SS + sq)) * DD + h * DKK;

    float q[DKK];
    #pragma unroll
    for (int k = 0; k < DKK; k += 4) {
        float4 v4 = *reinterpret_cast<const float4*>(qptr + k);
        q[k + 0] = v4.x * 0.125f;   // fold 1/sqrt(64)
        q[k + 1] = v4.y * 0.125f;
        q[k + 2] = v4.z * 0.125f;
        q[k + 3] = v4.w * 0.125f;
    }

    float m = -1e30f;
    float l = 0.f;
    float o[DKK] = {};

    const int kmax = blockIdx.x * RT + RT;   // exclusive key bound for this block

    for (int j0 = 0; j0 < kmax; j0 += TK) {
        __syncthreads();
        // cooperative tile load (coalesced float4)
        #pragma unroll
        for (int e = tid; e < TK * DKK / 4; e += RT) {
            const int j  = e >> 4;           // / (DKK/4)
            const int k4 = (e & 15) * 4;
            const long gbase = ((long)(b * SS + j0 + j)) * DD + h * DKK + k4;
            *reinterpret_cast<float4*>(&Ks[j][k4]) =
                *reinterpret_cast<const float4*>(K + gbase);
            *reinterpret_cast<float4*>(&Vs[j][k4]) =
                *reinterpret_cast<const float4*>(V + gbase);
        }
        __syncthreads();

        const int jend = min(TK, sq - j0 + 1);  // causal: keys j0..sq
        for (int j = 0; j < jend; j++) {
            float s = 0.f;
            #pragma unroll
            for (int k = 0; k < DKK; k++) s += q[k] * Ks[j][k];

            if (s > m) {                      // lazy rescale
                const float corr = __expf(m - s);
                m = s;
                l *= corr;
                #pragma unroll
                for (int k = 0; k < DKK; k++) o[k] *= corr;
            }
            const float p = __expf(s - m);
            l += p;
            #pragma unroll
            for (int k = 0; k < DKK; k++) o[k] += p * Vs[j][k];
        }
    }

    const float inv_l = 1.f / l;
    float* optr = O + ((long)(b * SS + sq)) * DD + h * DKK;
    #pragma unroll
    for (int k = 0; k < DKK; k += 4) {
        float4 v4;
        v4.x = o[k + 0] * inv_l;
        v4.y = o[k + 1] * inv_l;
        v4.z = o[k + 2] * inv_l;
        v4.w = o[k + 3] * inv_l;
        *reinterpret_cast<float4*>(optr + k) = v4;
    }
}

// ---------------------------------------------------------------------------
// Launch
// ---------------------------------------------------------------------------
extern "C" void kernel_launch(void* const* d_in, const int* in_sizes, int n_in,
                              void* d_out, int out_size) {
    const float* x   = (const float*)d_in[0];
    const int*   tp  = (const int*)  d_in[1];
    const float* Wq  = (const float*)d_in[2];
    const float* Wk  = (const float*)d_in[3];
    const float* Wv  = (const float*)d_in[4];
    const float* Wo  = (const float*)d_in[5];
    float* out = (float*)d_out;

    float *gQ, *gK, *gV, *gAO;
    cudaGetSymbolAddress((void**)&gQ,  g_Q);
    cudaGetSymbolAddress((void**)&gK,  g_K);
    cudaGetSymbolAddress((void**)&gV,  g_V);
    cudaGetSymbolAddress((void**)&gAO, g_AO);

    dim3 gblk(256);
    dim3 ggrid(DD / 64, MS / 64);   // (16, 128)

    // Projections
    gemm_abt_kernel<<<ggrid, gblk>>>(x, Wq, gQ, MS, DD, DD);
    gemm_abt_kernel<<<ggrid, gblk>>>(x, Wk, gK, MS, DD, DD);
    gemm_abt_kernel<<<ggrid, gblk>>>(x, Wv, gV, MS, DD, DD);

    // RoPE on Q and K
    {
        int total_pairs = MS * DD / 2;          // 4,194,304
        rope_kernel<<<total_pairs / 256, 256>>>(gQ, gK, tp);
    }

    // Causal flash attention
    {
        dim3 agrid(SS / 128, BB * HH);          // (16, 64)
        attn_kernel<<<agrid, 128>>>(gQ, gK, gV, gAO);
    }

    // Output projection
    gemm_abt_kernel<<<ggrid, gblk>>>(gAO, Wo, out, MS, DD, DD);
}

// round 11
// speedup vs baseline: 1.5130x; 1.5130x over previous
#include <cuda_runtime.h>
#include <cuda_bf16.h>
#include <math.h>
#include <stdint.h>

// Problem constants
#define BB 4
#define SS 2048
#define DD 1024
#define HH 16
#define DKK 64
#define MS (BB*SS)          // 8192 rows

// Scratch (static device arrays — no allocation at runtime)
__device__ float g_Q[MS*DD];
__device__ float g_K[MS*DD];
__device__ float g_V[MS*DD];
__device__ float g_AO[MS*DD];

// ===========================================================================
// Helpers
// ===========================================================================
__device__ __forceinline__ uint32_t smem_u32(const void* p) {
    uint32_t a;
    asm("{ .reg .u64 t; cvta.to.shared.u64 t, %1; cvt.u32.u64 %0, t; }"
        : "=r"(a) : "l"(p));
    return a;
}

__device__ __forceinline__ uint32_t sw128(uint32_t off) {
    return off ^ ((off >> 3) & 0x70);
}

__device__ __forceinline__ void ldsm_x4(uint32_t* r, uint32_t addr) {
    asm volatile("ldmatrix.sync.aligned.m8n8.x4.shared.b16 {%0,%1,%2,%3}, [%4];"
                 : "=r"(r[0]), "=r"(r[1]), "=r"(r[2]), "=r"(r[3]) : "r"(addr));
}

__device__ __forceinline__ void ldsm_x2(uint32_t* r, uint32_t addr) {
    asm volatile("ldmatrix.sync.aligned.m8n8.x2.shared.b16 {%0,%1}, [%2];"
                 : "=r"(r[0]), "=r"(r[1]) : "r"(addr));
}

// D = A(row m16k16) * B(col k16n8) + D, bf16 inputs, fp32 accum
__device__ __forceinline__ void mma16816(float* c, const uint32_t* a, const uint32_t* b) {
    asm volatile(
        "mma.sync.aligned.m16n8k16.row.col.f32.bf16.bf16.f32 "
        "{%0,%1,%2,%3}, {%4,%5,%6,%7}, {%8,%9}, {%0,%1,%2,%3};"
        : "+f"(c[0]), "+f"(c[1]), "+f"(c[2]), "+f"(c[3])
        : "r"(a[0]), "r"(a[1]), "r"(a[2]), "r"(a[3]), "r"(b[0]), "r"(b[1]));
}

// ===========================================================================
// mma.sync GEMM: C[M,N] = A[M,K] * W[N,K]^T, fp32 in/out, bf16x3 split.
// 128x128 CTA tile, 8 warps (2x4), warp tile 64x32, K-chunk 64.
// SW128-swizzled smem, double buffered, reg-staged global loads.
// ===========================================================================
#define KCHUNK 64
#define KITERS (DD / KCHUNK)          // 16
#define BUF_B  65536                  // aHi|aLo|bHi|bLo, each 128x128B = 16KB
#define SMEM_GEMM_SZ (2 * BUF_B)      // 131072

__device__ __forceinline__ void stage_regs(const float* __restrict__ A,
                                           const float* __restrict__ W,
                                           int row0, int col0, int k0, int t,
                                           uint4* rh, uint4* rl) {
    #pragma unroll
    for (int i = 0; i < 8; i++) {
        const int g   = t + i * 256;
        const bool isB = g >= 1024;
        const int gg  = g & 1023;
        const int row = gg >> 3;
        const int seg = gg & 7;
        const float* src = (isB ? W + (long)(col0 + row) * DD
                                : A + (long)(row0 + row) * DD) + k0 + seg * 8;
        float4 f0 = *reinterpret_cast<const float4*>(src);
        float4 f1 = *reinterpret_cast<const float4*>(src + 4);
        float f[8] = {f0.x, f0.y, f0.z, f0.w, f1.x, f1.y, f1.z, f1.w};
        uint32_t hi[4], lo[4];
        #pragma unroll
        for (int j = 0; j < 4; j++) {
            float a = f[2 * j], b = f[2 * j + 1];
            float ha = __bfloat162float(__float2bfloat16_rn(a));
            float hb = __bfloat162float(__float2bfloat16_rn(b));
            __nv_bfloat162 H = __floats2bfloat162_rn(ha, hb);
            __nv_bfloat162 L = __floats2bfloat162_rn(a - ha, b - hb);
            hi[j] = *reinterpret_cast<uint32_t*>(&H);
            lo[j] = *reinterpret_cast<uint32_t*>(&L);
        }
        rh[i] = make_uint4(hi[0], hi[1], hi[2], hi[3]);
        rl[i] = make_uint4(lo[0], lo[1], lo[2], lo[3]);
    }
}

__device__ __forceinline__ void store_smem(char* buf, int t,
                                           const uint4* rh, const uint4* rl) {
    #pragma unroll
    for (int i = 0; i < 8; i++) {
        const int g   = t + i * 256;
        const bool isB = g >= 1024;
        const int gg  = g & 1023;
        const int row = gg >> 3;
        const int seg = gg & 7;
        const uint32_t off = sw128((uint32_t)(row * 128 + seg * 16));
        char* dH = buf + (isB ? 32768 : 0);
        char* dL = buf + (isB ? 49152 : 16384);
        *reinterpret_cast<uint4*>(dH + off) = rh[i];
        *reinterpret_cast<uint4*>(dL + off) = rl[i];
    }
}

__device__ __forceinline__ void gemm_tile_mma(const float* __restrict__ A,
                                              const float* __restrict__ W,
                                              float* __restrict__ C,
                                              int row0, int col0) {
    extern __shared__ char smem[];
    const int t      = threadIdx.x;
    const int wid    = t >> 5;
    const int lane   = t & 31;
    const int warp_m = wid >> 2;       // 0..1
    const int warp_n = wid & 3;        // 0..3
    const uint32_t sb = smem_u32(smem);

    float acc[4][4][4] = {};
    uint4 rh[8], rl[8];

    // Prologue: stage + store chunk 0
    stage_regs(A, W, row0, col0, 0, t, rh, rl);
    store_smem(smem, t, rh, rl);

    for (int it = 0; it < KITERS; it++) {
        const int p = it & 1;
        if (it + 1 < KITERS)
            stage_regs(A, W, row0, col0, (it + 1) * KCHUNK, t, rh, rl);

        __syncthreads();               // buffer p fully stored

        const uint32_t saH = sb + p * BUF_B;
        const uint32_t saL = saH + 16384;
        const uint32_t sbH = saH + 32768;
        const uint32_t sbL = saH + 49152;

        #pragma unroll
        for (int ks = 0; ks < 4; ks++) {
            uint32_t AH[4][4], AL[4][4];
            #pragma unroll
            for (int mt = 0; mt < 4; mt++) {
                const int row = warp_m * 64 + mt * 16 + (lane & 15);
                const int kb  = ks * 32 + (lane >> 4) * 16;
                const uint32_t off = sw128((uint32_t)(row * 128 + kb));
                ldsm_x4(AH[mt], saH + off);
                ldsm_x4(AL[mt], saL + off);
            }
            #pragma unroll
            for (int nt = 0; nt < 4; nt++) {
                const int rowb = warp_n * 32 + nt * 8 + (lane & 7);
                const int kb   = ks * 32 + ((lane >> 3) & 1) * 16;
                const uint32_t off = sw128((uint32_t)(rowb * 128 + kb));
                uint32_t BH[2], BL[2];
                ldsm_x2(BH, sbH + off);
                ldsm_x2(BL, sbL + off);
                #pragma unroll
                for (int mt = 0; mt < 4; mt++) {
                    mma16816(acc[mt][nt], AH[mt], BH);
                    mma16816(acc[mt][nt], AH[mt], BL);
                    mma16816(acc[mt][nt], AL[mt], BH);
                }
            }
        }

        __syncthreads();               // all warps done reading buffer p

        if (it + 1 < KITERS)
            store_smem(smem + ((it + 1) & 1) * BUF_B, t, rh, rl);
    }

    // Epilogue: fragment -> global (float2 stores)
    const int fg = lane >> 2;          // 0..7
    const int tg = lane & 3;           // 0..3
    #pragma unroll
    for (int mt = 0; mt < 4; mt++) {
        #pragma unroll
        for (int nt = 0; nt < 4; nt++) {
            const long r = row0 + warp_m * 64 + mt * 16 + fg;
            const long c = col0 + warp_n * 32 + nt * 8 + tg * 2;
            *reinterpret_cast<float2*>(&C[r * DD + c]) =
                make_float2(acc[mt][nt][0], acc[mt][nt][1]);
            *reinterpret_cast<float2*>(&C[(r + 8) * DD + c]) =
                make_float2(acc[mt][nt][2], acc[mt][nt][3]);
        }
    }
}

__global__ __launch_bounds__(256)
void gemm_qkv_tc(const float* __restrict__ x,
                 const float* __restrict__ Wq,
                 const float* __restrict__ Wk,
                 const float* __restrict__ Wv) {
    const float* W;
    float* C;
    if (blockIdx.z == 0)      { W = Wq; C = g_Q; }
    else if (blockIdx.z == 1) { W = Wk; C = g_K; }
    else                      { W = Wv; C = g_V; }
    gemm_tile_mma(x, W, C, blockIdx.y * 128, blockIdx.x * 128);
}

__global__ __launch_bounds__(256)
void gemm_out_tc(const float* __restrict__ A,
                 const float* __restrict__ Wo,
                 float* __restrict__ C) {
    gemm_tile_mma(A, Wo, C, blockIdx.y * 128, blockIdx.x * 128);
}

// ---------------------------------------------------------------------------
// RoPE applied in-place to Q and K. Layout: [B, S, H, DK].
// ---------------------------------------------------------------------------
__global__ void rope_kernel(float* __restrict__ Q, float* __restrict__ K,
                            const int* __restrict__ pos) {
    const int idx = blockIdx.x * blockDim.x + threadIdx.x;
    const int i  = idx & 31;
    const int h  = (idx >> 5) & (HH - 1);
    const int bs = idx >> 9;
    const int s  = bs & (SS - 1);

    const float p = (float)pos[s];
    const float inv = exp2f(-(float)i * 0.4152410118607953f);
    const float ang = p * inv;
    float sn, cs;
    sincosf(ang, &sn, &cs);

    const long base = (long)bs * DD + h * DKK + 2 * i;

    float q1 = Q[base], q2 = Q[base + 1];
    Q[base]     = q1 * cs - q2 * sn;
    Q[base + 1] = q1 * sn + q2 * cs;

    float k1 = K[base], k2 = K[base + 1];
    K[base]     = k1 * cs - k2 * sn;
    K[base + 1] = k1 * sn + k2 * cs;
}

// ---------------------------------------------------------------------------
// Causal flash attention, fp32, one thread per query row (float4 inner loops)
// ---------------------------------------------------------------------------
__global__ __launch_bounds__(128)
void attn_kernel(const float* __restrict__ Q,
                 const float* __restrict__ K,
                 const float* __restrict__ V,
                 float* __restrict__ O) {
    constexpr int RT = 128;
    constexpr int TK = 64;

    __shared__ float Ks[TK][DKK];
    __shared__ float Vs[TK][DKK];

    const int tid = threadIdx.x;
    const int bh  = blockIdx.y;
    const int b   = bh >> 4;
    const int h   = bh & (HH - 1);
    const int sq  = blockIdx.x * RT + tid;

    const float* qptr = Q + ((long)(b * SS + sq)) * DD + h * DKK;

    float q[DKK];
    #pragma unroll
    for (int k = 0; k < DKK; k += 4) {
        float4 v4 = *reinterpret_cast<const float4*>(qptr + k);
        q[k + 0] = v4.x * 0.125f;
        q[k + 1] = v4.y * 0.125f;
        q[k + 2] = v4.z * 0.125f;
        q[k + 3] = v4.w * 0.125f;
    }

    float m = -1e30f;
    float l = 0.f;
    float o[DKK] = {};

    const int kmax = blockIdx.x * RT + RT;

    for (int j0 = 0; j0 < kmax; j0 += TK) {
        __syncthreads();
        #pragma unroll
        for (int e = tid; e < TK * DKK / 4; e += RT) {
            const int j  = e >> 4;
            const int k4 = (e & 15) * 4;
            const long gbase = ((long)(b * SS + j0 + j)) * DD + h * DKK + k4;
            *reinterpret_cast<float4*>(&Ks[j][k4]) =
                *reinterpret_cast<const float4*>(K + gbase);
            *reinterpret_cast<float4*>(&Vs[j][k4]) =
                *reinterpret_cast<const float4*>(V + gbase);
        }
        __syncthreads();

        const int jend = min(TK, sq - j0 + 1);
        for (int j = 0; j < jend; j++) {
            const float4* K4 = reinterpret_cast<const float4*>(&Ks[j][0]);
            float s = 0.f;
            #pragma unroll
            for (int kk = 0; kk < 16; kk++) {
                float4 kv = K4[kk];
                s += q[4 * kk + 0] * kv.x + q[4 * kk + 1] * kv.y
                   + q[4 * kk + 2] * kv.z + q[4 * kk + 3] * kv.w;
            }

            if (s > m) {
                const float corr = __expf(m - s);
                m = s;
                l *= corr;
                #pragma unroll
                for (int k = 0; k < DKK; k++) o[k] *= corr;
            }
            const float p = __expf(s - m);
            l += p;
            const float4* V4 = reinterpret_cast<const float4*>(&Vs[j][0]);
            #pragma unroll
            for (int kk = 0; kk < 16; kk++) {
                float4 vv = V4[kk];
                o[4 * kk + 0] += p * vv.x;
                o[4 * kk + 1] += p * vv.y;
                o[4 * kk + 2] += p * vv.z;
                o[4 * kk + 3] += p * vv.w;
            }
        }
    }

    const float inv_l = 1.f / l;
    float* optr = O + ((long)(b * SS + sq)) * DD + h * DKK;
    #pragma unroll
    for (int k = 0; k < DKK; k += 4) {
        float4 v4;
        v4.x = o[k + 0] * inv_l;
        v4.y = o[k + 1] * inv_l;
        v4.z = o[k + 2] * inv_l;
        v4.w = o[k + 3] * inv_l;
        *reinterpret_cast<float4*>(optr + k) = v4;
    }
}

// ---------------------------------------------------------------------------
// Launch
// ---------------------------------------------------------------------------
extern "C" void kernel_launch(void* const* d_in, const int* in_sizes, int n_in,
                              void* d_out, int out_size) {
    const float* x   = (const float*)d_in[0];
    const int*   tp  = (const int*)  d_in[1];
    const float* Wq  = (const float*)d_in[2];
    const float* Wk  = (const float*)d_in[3];
    const float* Wv  = (const float*)d_in[4];
    const float* Wo  = (const float*)d_in[5];
    float* out = (float*)d_out;

    float *gQ, *gK, *gV, *gAO;
    cudaGetSymbolAddress((void**)&gQ,  g_Q);
    cudaGetSymbolAddress((void**)&gK,  g_K);
    cudaGetSymbolAddress((void**)&gV,  g_V);
    cudaGetSymbolAddress((void**)&gAO, g_AO);

    cudaFuncSetAttribute(gemm_qkv_tc, cudaFuncAttributeMaxDynamicSharedMemorySize,
                         SMEM_GEMM_SZ);
    cudaFuncSetAttribute(gemm_out_tc, cudaFuncAttributeMaxDynamicSharedMemorySize,
                         SMEM_GEMM_SZ);

    // QKV projections (mma.sync bf16x3)
    {
        dim3 grid(DD / 128, MS / 128, 3);   // (8, 64, 3)
        gemm_qkv_tc<<<grid, 256, SMEM_GEMM_SZ>>>(x, Wq, Wk, Wv);
    }

    // RoPE on Q and K
    {
        int total_pairs = MS * DD / 2;
        rope_kernel<<<total_pairs / 256, 256>>>(gQ, gK, tp);
    }

    // Causal flash attention
    {
        dim3 agrid(SS / 128, BB * HH);
        attn_kernel<<<agrid, 128>>>(gQ, gK, gV, gAO);
    }

    // Output projection (mma.sync bf16x3)
    {
        dim3 grid(DD / 128, MS / 128);      // (8, 64)
        gemm_out_tc<<<grid, 256, SMEM_GEMM_SZ>>>(gAO, Wo, out);
    }
}

// round 13
// speedup vs baseline: 2.3951x; 1.5831x over previous
#include <cuda_runtime.h>
#include <cuda_bf16.h>
#include <math.h>
#include <stdint.h>

// Problem constants
#define BB 4
#define SS 2048
#define DD 1024
#define HH 16
#define DKK 64
#define MS (BB*SS)          // 8192 rows

// Scratch (static device arrays — no allocation at runtime)
__device__ float g_Q[MS*DD];
__device__ float g_K[MS*DD];
__device__ float g_V[MS*DD];
__device__ float g_AO[MS*DD];

// ===========================================================================
// Helpers
// ===========================================================================
__device__ __forceinline__ uint32_t smem_u32(const void* p) {
    uint32_t a;
    asm("{ .reg .u64 t; cvta.to.shared.u64 t, %1; cvt.u32.u64 %0, t; }"
        : "=r"(a) : "l"(p));
    return a;
}

__device__ __forceinline__ uint32_t sw128(uint32_t off) {
    return off ^ ((off >> 3) & 0x70);
}

__device__ __forceinline__ void ldsm_x4(uint32_t* r, uint32_t addr) {
    asm volatile("ldmatrix.sync.aligned.m8n8.x4.shared.b16 {%0,%1,%2,%3}, [%4];"
                 : "=r"(r[0]), "=r"(r[1]), "=r"(r[2]), "=r"(r[3]) : "r"(addr));
}

__device__ __forceinline__ void ldsm_x2(uint32_t* r, uint32_t addr) {
    asm volatile("ldmatrix.sync.aligned.m8n8.x2.shared.b16 {%0,%1}, [%2];"
                 : "=r"(r[0]), "=r"(r[1]) : "r"(addr));
}

// D = A(row m16k16) * B(col k16n8) + D, bf16 inputs, fp32 accum
__device__ __forceinline__ void mma16816(float* c, const uint32_t* a, const uint32_t* b) {
    asm volatile(
        "mma.sync.aligned.m16n8k16.row.col.f32.bf16.bf16.f32 "
        "{%0,%1,%2,%3}, {%4,%5,%6,%7}, {%8,%9}, {%0,%1,%2,%3};"
        : "+f"(c[0]), "+f"(c[1]), "+f"(c[2]), "+f"(c[3])
        : "r"(a[0]), "r"(a[1]), "r"(a[2]), "r"(a[3]), "r"(b[0]), "r"(b[1]));
}

__device__ __forceinline__ uint32_t pack_bf16x2(float a, float b) {
    __nv_bfloat162 h = __floats2bfloat162_rn(a, b);
    return *reinterpret_cast<uint32_t*>(&h);
}

// ===========================================================================
// mma.sync GEMM: C[M,N] = A[M,K] * W[N,K]^T, fp32 in/out, bf16x3 split.
// ===========================================================================
#define KCHUNK 64
#define KITERS (DD / KCHUNK)          // 16
#define BUF_B  65536
#define SMEM_GEMM_SZ (2 * BUF_B)      // 131072

__device__ __forceinline__ void stage_regs(const float* __restrict__ A,
                                           const float* __restrict__ W,
                                           int row0, int col0, int k0, int t,
                                           uint4* rh, uint4* rl) {
    #pragma unroll
    for (int i = 0; i < 8; i++) {
        const int g   = t + i * 256;
        const bool isB = g >= 1024;
        const int gg  = g & 1023;
        const int row = gg >> 3;
        const int seg = gg & 7;
        const float* src = (isB ? W + (long)(col0 + row) * DD
                                : A + (long)(row0 + row) * DD) + k0 + seg * 8;
        float4 f0 = *reinterpret_cast<const float4*>(src);
        float4 f1 = *reinterpret_cast<const float4*>(src + 4);
        float f[8] = {f0.x, f0.y, f0.z, f0.w, f1.x, f1.y, f1.z, f1.w};
        uint32_t hi[4], lo[4];
        #pragma unroll
        for (int j = 0; j < 4; j++) {
            float a = f[2 * j], b = f[2 * j + 1];
            float ha = __bfloat162float(__float2bfloat16_rn(a));
            float hb = __bfloat162float(__float2bfloat16_rn(b));
            hi[j] = pack_bf16x2(ha, hb);
            lo[j] = pack_bf16x2(a - ha, b - hb);
        }
        rh[i] = make_uint4(hi[0], hi[1], hi[2], hi[3]);
        rl[i] = make_uint4(lo[0], lo[1], lo[2], lo[3]);
    }
}

__device__ __forceinline__ void store_smem(char* buf, int t,
                                           const uint4* rh, const uint4* rl) {
    #pragma unroll
    for (int i = 0; i < 8; i++) {
        const int g   = t + i * 256;
        const bool isB = g >= 1024;
        const int gg  = g & 1023;
        const int row = gg >> 3;
        const int seg = gg & 7;
        const uint32_t off = sw128((uint32_t)(row * 128 + seg * 16));
        char* dH = buf + (isB ? 32768 : 0);
        char* dL = buf + (isB ? 49152 : 16384);
        *reinterpret_cast<uint4*>(dH + off) = rh[i];
        *reinterpret_cast<uint4*>(dL + off) = rl[i];
    }
}

__device__ __forceinline__ void gemm_tile_mma(const float* __restrict__ A,
                                              const float* __restrict__ W,
                                              float* __restrict__ C,
                                              int row0, int col0) {
    extern __shared__ char smem[];
    const int t      = threadIdx.x;
    const int wid    = t >> 5;
    const int lane   = t & 31;
    const int warp_m = wid >> 2;
    const int warp_n = wid & 3;
    const uint32_t sb = smem_u32(smem);

    float acc[4][4][4] = {};
    uint4 rh[8], rl[8];

    stage_regs(A, W, row0, col0, 0, t, rh, rl);
    store_smem(smem, t, rh, rl);

    for (int it = 0; it < KITERS; it++) {
        const int p = it & 1;
        if (it + 1 < KITERS)
            stage_regs(A, W, row0, col0, (it + 1) * KCHUNK, t, rh, rl);

        __syncthreads();

        const uint32_t saH = sb + p * BUF_B;
        const uint32_t saL = saH + 16384;
        const uint32_t sbH = saH + 32768;
        const uint32_t sbL = saH + 49152;

        #pragma unroll
        for (int ks = 0; ks < 4; ks++) {
            uint32_t AH[4][4], AL[4][4];
            #pragma unroll
            for (int mt = 0; mt < 4; mt++) {
                const int row = warp_m * 64 + mt * 16 + (lane & 15);
                const int kb  = ks * 32 + (lane >> 4) * 16;
                const uint32_t off = sw128((uint32_t)(row * 128 + kb));
                ldsm_x4(AH[mt], saH + off);
                ldsm_x4(AL[mt], saL + off);
            }
            #pragma unroll
            for (int nt = 0; nt < 4; nt++) {
                const int rowb = warp_n * 32 + nt * 8 + (lane & 7);
                const int kb   = ks * 32 + ((lane >> 3) & 1) * 16;
                const uint32_t off = sw128((uint32_t)(rowb * 128 + kb));
                uint32_t BH[2], BL[2];
                ldsm_x2(BH, sbH + off);
                ldsm_x2(BL, sbL + off);
                #pragma unroll
                for (int mt = 0; mt < 4; mt++) {
                    mma16816(acc[mt][nt], AH[mt], BH);
                    mma16816(acc[mt][nt], AH[mt], BL);
                    mma16816(acc[mt][nt], AL[mt], BH);
                }
            }
        }

        __syncthreads();

        if (it + 1 < KITERS)
            store_smem(smem + ((it + 1) & 1) * BUF_B, t, rh, rl);
    }

    const int fg = lane >> 2;
    const int tg = lane & 3;
    #pragma unroll
    for (int mt = 0; mt < 4; mt++) {
        #pragma unroll
        for (int nt = 0; nt < 4; nt++) {
            const long r = row0 + warp_m * 64 + mt * 16 + fg;
            const long c = col0 + warp_n * 32 + nt * 8 + tg * 2;
            *reinterpret_cast<float2*>(&C[r * DD + c]) =
                make_float2(acc[mt][nt][0], acc[mt][nt][1]);
            *reinterpret_cast<float2*>(&C[(r + 8) * DD + c]) =
                make_float2(acc[mt][nt][2], acc[mt][nt][3]);
        }
    }
}

__global__ __launch_bounds__(256)
void gemm_qkv_tc(const float* __restrict__ x,
                 const float* __restrict__ Wq,
                 const float* __restrict__ Wk,
                 const float* __restrict__ Wv) {
    const float* W;
    float* C;
    if (blockIdx.z == 0)      { W = Wq; C = g_Q; }
    else if (blockIdx.z == 1) { W = Wk; C = g_K; }
    else                      { W = Wv; C = g_V; }
    gemm_tile_mma(x, W, C, blockIdx.y * 128, blockIdx.x * 128);
}

__global__ __launch_bounds__(256)
void gemm_out_tc(const float* __restrict__ A,
                 const float* __restrict__ Wo,
                 float* __restrict__ C) {
    gemm_tile_mma(A, Wo, C, blockIdx.y * 128, blockIdx.x * 128);
}

// ---------------------------------------------------------------------------
// RoPE applied in-place to Q and K. Layout: [B, S, H, DK].
// ---------------------------------------------------------------------------
__global__ void rope_kernel(float* __restrict__ Q, float* __restrict__ K,
                            const int* __restrict__ pos) {
    const int idx = blockIdx.x * blockDim.x + threadIdx.x;
    const int i  = idx & 31;
    const int h  = (idx >> 5) & (HH - 1);
    const int bs = idx >> 9;
    const int s  = bs & (SS - 1);

    const float p = (float)pos[s];
    const float inv = exp2f(-(float)i * 0.4152410118607953f);
    const float ang = p * inv;
    float sn, cs;
    sincosf(ang, &sn, &cs);

    const long base = (long)bs * DD + h * DKK + 2 * i;

    float q1 = Q[base], q2 = Q[base + 1];
    Q[base]     = q1 * cs - q2 * sn;
    Q[base + 1] = q1 * sn + q2 * cs;

    float k1 = K[base], k2 = K[base + 1];
    K[base]     = k1 * cs - k2 * sn;
    K[base + 1] = k1 * sn + k2 * cs;
}

// ===========================================================================
// Tensor-core causal flash attention (mma.sync, bf16x3)
// Block: 256 thr = 8 warps; each warp owns 16 query rows (128 rows/block).
// Per 64-key tile: K hi/lo + V-transposed hi/lo staged in 32KB smem.
// ===========================================================================
#define SMEM_ATT 32768

__global__ __launch_bounds__(256)
void attn_mma_kernel(const float* __restrict__ Q,
                     const float* __restrict__ K,
                     const float* __restrict__ V,
                     float* __restrict__ O) {
    __shared__ char sm[SMEM_ATT];
    const uint32_t sb = smem_u32(sm);

    const int t    = threadIdx.x;
    const int w    = t >> 5;
    const int lane = t & 31;
    const int g    = lane >> 2;       // row group 0..7
    const int tg   = lane & 3;

    const int qi    = gridDim.x - 1 - blockIdx.x;   // heavy tiles first
    const int bh    = blockIdx.y;
    const int b     = bh >> 4;
    const int h     = bh & (HH - 1);
    const int row0g = qi * 128;                     // global q row base
    const long rowbase = (long)b * SS;
    const long hoff = h * DKK;

    // ---- Stage Q (scaled by 1/8, hi/lo split) into smem, then to fragments
    {
        char* QH = sm;
        char* QL = sm + 16384;
        #pragma unroll
        for (int i = 0; i < 8; i++) {
            const int gidx = t + i * 256;           // 0..2047
            const int row = gidx >> 4;
            const int seg = gidx & 15;
            const float4 v4 = *reinterpret_cast<const float4*>(
                Q + (rowbase + row0g + row) * DD + hoff + seg * 4);
            float f[4] = {v4.x * 0.125f, v4.y * 0.125f, v4.z * 0.125f, v4.w * 0.125f};
            float h0 = __bfloat162float(__float2bfloat16_rn(f[0]));
            float h1 = __bfloat162float(__float2bfloat16_rn(f[1]));
            float h2 = __bfloat162float(__float2bfloat16_rn(f[2]));
            float h3 = __bfloat162float(__float2bfloat16_rn(f[3]));
            uint2 hv = make_uint2(pack_bf16x2(h0, h1), pack_bf16x2(h2, h3));
            uint2 lv = make_uint2(pack_bf16x2(f[0] - h0, f[1] - h1),
                                  pack_bf16x2(f[2] - h2, f[3] - h3));
            const uint32_t off = sw128((uint32_t)(row * 128 + seg * 8));
            *reinterpret_cast<uint2*>(QH + off) = hv;
            *reinterpret_cast<uint2*>(QL + off) = lv;
        }
    }
    __syncthreads();

    uint32_t QHf[4][4], QLf[4][4];
    #pragma unroll
    for (int kt = 0; kt < 4; kt++) {
        const int row = w * 16 + (lane & 15);
        const int kb  = kt * 32 + (lane >> 4) * 16;
        const uint32_t off = sw128((uint32_t)(row * 128 + kb));
        ldsm_x4(QHf[kt], sb + off);
        ldsm_x4(QLf[kt], sb + 16384 + off);
    }

    // ---- Online softmax state
    float m0 = -1e30f, m1 = -1e30f, l0 = 0.f, l1 = 0.f;
    float Oacc[8][4] = {};

    const int qbase = row0g + w * 16;
    const int qmax_w = qbase + 15;
    const int kend = row0g + 128;

    const uint32_t KH  = sb;
    const uint32_t KL  = sb + 8192;
    const uint32_t VtH = sb + 16384;
    const uint32_t VtL = sb + 24576;

    for (int j0 = 0; j0 < kend; j0 += 64) {
        __syncthreads();   // previous tile's reads complete

        // ---- Stage K tile (64 keys x 64 dk), hi/lo, SW128
        #pragma unroll
        for (int i = 0; i < 4; i++) {
            const int gidx = t + i * 256;           // 0..1023
            const int row = gidx >> 4;              // key
            const int seg = gidx & 15;
            const float4 v4 = *reinterpret_cast<const float4*>(
                K + (rowbase + j0 + row) * DD + hoff + seg * 4);
            float h0 = __bfloat162float(__float2bfloat16_rn(v4.x));
            float h1 = __bfloat162float(__float2bfloat16_rn(v4.y));
            float h2 = __bfloat162float(__float2bfloat16_rn(v4.z));
            float h3 = __bfloat162float(__float2bfloat16_rn(v4.w));
            const uint32_t off = sw128((uint32_t)(row * 128 + seg * 8));
            *reinterpret_cast<uint2*>(sm + (KH - sb) + off) =
                make_uint2(pack_bf16x2(h0, h1), pack_bf16x2(h2, h3));
            *reinterpret_cast<uint2*>(sm + (KL - sb) + off) =
                make_uint2(pack_bf16x2(v4.x - h0, v4.y - h1),
                           pack_bf16x2(v4.z - h2, v4.w - h3));
        }
        // ---- Stage V tile transposed: Vt[dk][key], hi/lo
        #pragma unroll
        for (int i = 0; i < 2; i++) {
            const int u  = t + i * 256;             // 0..511
            const int dg = u & 15;                  // dk group of 4
            const int kp = u >> 4;                  // key pair 0..31
            const float4 v0 = *reinterpret_cast<const float4*>(
                V + (rowbase + j0 + 2 * kp) * DD + hoff + dg * 4);
            const float4 v1 = *reinterpret_cast<const float4*>(
                V + (rowbase + j0 + 2 * kp + 1) * DD + hoff + dg * 4);
            const float a0[4] = {v0.x, v0.y, v0.z, v0.w};
            const float a1[4] = {v1.x, v1.y, v1.z, v1.w};
            #pragma unroll
            for (int jj = 0; jj < 4; jj++) {
                const int d = dg * 4 + jj;
                float h0 = __bfloat162float(__float2bfloat16_rn(a0[jj]));
                float h1 = __bfloat162float(__float2bfloat16_rn(a1[jj]));
                const uint32_t off = sw128((uint32_t)(d * 128 + kp * 4));
                *reinterpret_cast<uint32_t*>(sm + (VtH - sb) + off) = pack_bf16x2(h0, h1);
                *reinterpret_cast<uint32_t*>(sm + (VtL - sb) + off) =
                    pack_bf16x2(a0[jj] - h0, a1[jj] - h1);
            }
        }
        __syncthreads();   // tile staged

        if (j0 > qmax_w) continue;   // fully masked for this warp

        // ---- S = Q K^T  (16 x 64), bf16x3
        float Sacc[8][4] = {};
        #pragma unroll
        for (int nt = 0; nt < 8; nt++) {
            #pragma unroll
            for (int ks = 0; ks < 4; ks++) {
                const int rowb = nt * 8 + (lane & 7);
                const int kb   = ks * 32 + ((lane >> 3) & 1) * 16;
                const uint32_t off = sw128((uint32_t)(rowb * 128 + kb));
                uint32_t BH[2], BL[2];
                ldsm_x2(BH, KH + off);
                ldsm_x2(BL, KL + off);
                mma16816(Sacc[nt], QHf[ks], BH);
                mma16816(Sacc[nt], QHf[ks], BL);
                mma16816(Sacc[nt], QLf[ks], BH);
            }
        }

        // ---- Mask + online softmax
        const bool need_mask = (j0 + 63 > qbase);
        float rmax0 = -1e30f, rmax1 = -1e30f;
        #pragma unroll
        for (int nt = 0; nt < 8; nt++) {
            if (need_mask) {
                const int c0 = j0 + nt * 8 + tg * 2;
                const int q0 = qbase + g;
                if (c0     > q0)     Sacc[nt][0] = -1e30f;
                if (c0 + 1 > q0)     Sacc[nt][1] = -1e30f;
                if (c0     > q0 + 8) Sacc[nt][2] = -1e30f;
                if (c0 + 1 > q0 + 8) Sacc[nt][3] = -1e30f;
            }
            rmax0 = fmaxf(rmax0, fmaxf(Sacc[nt][0], Sacc[nt][1]));
            rmax1 = fmaxf(rmax1, fmaxf(Sacc[nt][2], Sacc[nt][3]));
        }
        rmax0 = fmaxf(rmax0, __shfl_xor_sync(0xffffffffu, rmax0, 1));
        rmax0 = fmaxf(rmax0, __shfl_xor_sync(0xffffffffu, rmax0, 2));
        rmax1 = fmaxf(rmax1, __shfl_xor_sync(0xffffffffu, rmax1, 1));
        rmax1 = fmaxf(rmax1, __shfl_xor_sync(0xffffffffu, rmax1, 2));

        const float m0n = fmaxf(m0, rmax0);
        const float m1n = fmaxf(m1, rmax1);
        const float corr0 = __expf(m0 - m0n);
        const float corr1 = __expf(m1 - m1n);
        m0 = m0n; m1 = m1n;

        float rsum0 = 0.f, rsum1 = 0.f;
        #pragma unroll
        for (int nt = 0; nt < 8; nt++) {
            Sacc[nt][0] = __expf(Sacc[nt][0] - m0);
            Sacc[nt][1] = __expf(Sacc[nt][1] - m0);
            Sacc[nt][2] = __expf(Sacc[nt][2] - m1);
            Sacc[nt][3] = __expf(Sacc[nt][3] - m1);
            rsum0 += Sacc[nt][0] + Sacc[nt][1];
            rsum1 += Sacc[nt][2] + Sacc[nt][3];
        }
        rsum0 += __shfl_xor_sync(0xffffffffu, rsum0, 1);
        rsum0 += __shfl_xor_sync(0xffffffffu, rsum0, 2);
        rsum1 += __shfl_xor_sync(0xffffffffu, rsum1, 1);
        rsum1 += __shfl_xor_sync(0xffffffffu, rsum1, 2);
        l0 = l0 * corr0 + rsum0;
        l1 = l1 * corr1 + rsum1;

        #pragma unroll
        for (int nt = 0; nt < 8; nt++) {
            Oacc[nt][0] *= corr0;
            Oacc[nt][1] *= corr0;
            Oacc[nt][2] *= corr1;
            Oacc[nt][3] *= corr1;
        }

        // ---- P fragments (hi/lo): C-layout of two n8 tiles == A-layout m16k16
        uint32_t PH[4][4], PL[4][4];
        #pragma unroll
        for (int ks = 0; ks < 4; ks++) {
            #pragma unroll
            for (int half = 0; half < 2; half++) {
                const float* S = Sacc[2 * ks + half];
                float h0 = __bfloat162float(__float2bfloat16_rn(S[0]));
                float h1 = __bfloat162float(__float2bfloat16_rn(S[1]));
                float h2 = __bfloat162float(__float2bfloat16_rn(S[2]));
                float h3 = __bfloat162float(__float2bfloat16_rn(S[3]));
                PH[ks][2 * half + 0] = pack_bf16x2(h0, h1);
                PH[ks][2 * half + 1] = pack_bf16x2(h2, h3);
                PL[ks][2 * half + 0] = pack_bf16x2(S[0] - h0, S[1] - h1);
                PL[ks][2 * half + 1] = pack_bf16x2(S[2] - h2, S[3] - h3);
            }
        }

        // ---- O += P V   (16 x 64), bf16x3
        #pragma unroll
        for (int nt = 0; nt < 8; nt++) {
            #pragma unroll
            for (int ks = 0; ks < 4; ks++) {
                const int rowb = nt * 8 + (lane & 7);
                const int kb   = ks * 32 + ((lane >> 3) & 1) * 16;
                const uint32_t off = sw128((uint32_t)(rowb * 128 + kb));
                uint32_t VHf[2], VLf[2];
                ldsm_x2(VHf, VtH + off);
                ldsm_x2(VLf, VtL + off);
                mma16816(Oacc[nt], PH[ks], VHf);
                mma16816(Oacc[nt], PH[ks], VLf);
                mma16816(Oacc[nt], PL[ks], VHf);
            }
        }
    }

    // ---- Epilogue
    const float inv0 = 1.f / l0;
    const float inv1 = 1.f / l1;
    #pragma unroll
    for (int nt = 0; nt < 8; nt++) {
        const long r0 = rowbase + qbase + g;
        const long c  = hoff + nt * 8 + tg * 2;
        *reinterpret_cast<float2*>(&O[r0 * DD + c]) =
            make_float2(Oacc[nt][0] * inv0, Oacc[nt][1] * inv0);
        *reinterpret_cast<float2*>(&O[(r0 + 8) * DD + c]) =
            make_float2(Oacc[nt][2] * inv1, Oacc[nt][3] * inv1);
    }
}

// ---------------------------------------------------------------------------
// Launch
// ---------------------------------------------------------------------------
extern "C" void kernel_launch(void* const* d_in, const int* in_sizes, int n_in,
                              void* d_out, int out_size) {
    const float* x   = (const float*)d_in[0];
    const int*   tp  = (const int*)  d_in[1];
    const float* Wq  = (const float*)d_in[2];
    const float* Wk  = (const float*)d_in[3];
    const float* Wv  = (const float*)d_in[4];
    const float* Wo  = (const float*)d_in[5];
    float* out = (float*)d_out;

    float *gQ, *gK, *gV, *gAO;
    cudaGetSymbolAddress((void**)&gQ,  g_Q);
    cudaGetSymbolAddress((void**)&gK,  g_K);
    cudaGetSymbolAddress((void**)&gV,  g_V);
    cudaGetSymbolAddress((void**)&gAO, g_AO);

    cudaFuncSetAttribute(gemm_qkv_tc, cudaFuncAttributeMaxDynamicSharedMemorySize,
                         SMEM_GEMM_SZ);
    cudaFuncSetAttribute(gemm_out_tc, cudaFuncAttributeMaxDynamicSharedMemorySize,
                         SMEM_GEMM_SZ);

    // QKV projections (mma.sync bf16x3)
    {
        dim3 grid(DD / 128, MS / 128, 3);
        gemm_qkv_tc<<<grid, 256, SMEM_GEMM_SZ>>>(x, Wq, Wk, Wv);
    }

    // RoPE on Q and K
    {
        int total_pairs = MS * DD / 2;
        rope_kernel<<<total_pairs / 256, 256>>>(gQ, gK, tp);
    }

    // Causal flash attention (mma.sync bf16x3)
    {
        dim3 agrid(SS / 128, BB * HH);
        attn_mma_kernel<<<agrid, 256>>>(gQ, gK, gV, gAO);
    }

    // Output projection (mma.sync bf16x3)
    {
        dim3 grid(DD / 128, MS / 128);
        gemm_out_tc<<<grid, 256, SMEM_GEMM_SZ>>>(gAO, Wo, out);
    }
}

// round 15
// speedup vs baseline: 3.0591x; 1.2772x over previous
#include <cuda_runtime.h>
#include <cuda_bf16.h>
#include <math.h>
#include <stdint.h>

// Problem constants
#define BB 4
#define SS 2048
#define DD 1024
#define HH 16
#define DKK 64
#define MS (BB*SS)          // 8192 rows

// Scratch (static device arrays — no allocation at runtime)
__device__ float g_Q[MS*DD];
__device__ float g_K[MS*DD];
__device__ float g_V[MS*DD];
__device__ float g_AO[MS*DD];

// Pre-split bf16 hi/lo operands
__device__ __nv_bfloat16 g_xH[MS*DD],  g_xL[MS*DD];
__device__ __nv_bfloat16 g_aoH[MS*DD], g_aoL[MS*DD];
__device__ __nv_bfloat16 g_wqH[DD*DD], g_wqL[DD*DD];
__device__ __nv_bfloat16 g_wkH[DD*DD], g_wkL[DD*DD];
__device__ __nv_bfloat16 g_wvH[DD*DD], g_wvL[DD*DD];
__device__ __nv_bfloat16 g_woH[DD*DD], g_woL[DD*DD];

// ===========================================================================
// Helpers
// ===========================================================================
__device__ __forceinline__ uint32_t smem_u32(const void* p) {
    uint32_t a;
    asm("{ .reg .u64 t; cvta.to.shared.u64 t, %1; cvt.u32.u64 %0, t; }"
        : "=r"(a) : "l"(p));
    return a;
}

__device__ __forceinline__ uint32_t sw128(uint32_t off) {
    return off ^ ((off >> 3) & 0x70);
}

__device__ __forceinline__ void ldsm_x4(uint32_t* r, uint32_t addr) {
    asm volatile("ldmatrix.sync.aligned.m8n8.x4.shared.b16 {%0,%1,%2,%3}, [%4];"
                 : "=r"(r[0]), "=r"(r[1]), "=r"(r[2]), "=r"(r[3]) : "r"(addr));
}

__device__ __forceinline__ void ldsm_x2(uint32_t* r, uint32_t addr) {
    asm volatile("ldmatrix.sync.aligned.m8n8.x2.shared.b16 {%0,%1}, [%2];"
                 : "=r"(r[0]), "=r"(r[1]) : "r"(addr));
}

__device__ __forceinline__ void mma16816(float* c, const uint32_t* a, const uint32_t* b) {
    asm volatile(
        "mma.sync.aligned.m16n8k16.row.col.f32.bf16.bf16.f32 "
        "{%0,%1,%2,%3}, {%4,%5,%6,%7}, {%8,%9}, {%0,%1,%2,%3};"
        : "+f"(c[0]), "+f"(c[1]), "+f"(c[2]), "+f"(c[3])
        : "r"(a[0]), "r"(a[1]), "r"(a[2]), "r"(a[3]), "r"(b[0]), "r"(b[1]));
}

__device__ __forceinline__ uint32_t pack_bf16x2(float a, float b) {
    __nv_bfloat162 h = __floats2bfloat162_rn(a, b);
    return *reinterpret_cast<uint32_t*>(&h);
}

__device__ __forceinline__ void cp_async16(uint32_t dst, const void* src) {
    asm volatile("cp.async.cg.shared.global [%0], [%1], 16;"
                 :: "r"(dst), "l"(src));
}
#define CP_COMMIT() asm volatile("cp.async.commit_group;" ::: "memory")
#define CP_WAIT(n)  asm volatile("cp.async.wait_group %0;" :: "n"(n) : "memory")

// ===========================================================================
// Split pass: fp32 -> (bf16 hi, bf16 lo) elementwise, float4-vectorized
// ===========================================================================
__global__ __launch_bounds__(256)
void split_kernel(const float* __restrict__ src,
                  __nv_bfloat16* __restrict__ hi,
                  __nv_bfloat16* __restrict__ lo) {
    const int idx = blockIdx.x * blockDim.x + threadIdx.x;   // one float4
    const float4 v = reinterpret_cast<const float4*>(src)[idx];
    const float f[4] = {v.x, v.y, v.z, v.w};
    float h[4];
    #pragma unroll
    for (int j = 0; j < 4; j++)
        h[j] = __bfloat162float(__float2bfloat16_rn(f[j]));
    reinterpret_cast<uint2*>(hi)[idx] =
        make_uint2(pack_bf16x2(h[0], h[1]), pack_bf16x2(h[2], h[3]));
    reinterpret_cast<uint2*>(lo)[idx] =
        make_uint2(pack_bf16x2(f[0] - h[0], f[1] - h[1]),
                   pack_bf16x2(f[2] - h[2], f[3] - h[3]));
}

// ===========================================================================
// cp.async tensor-core GEMM: C[M,N] = A[M,K] * W[N,K]^T, pre-split bf16 hi/lo.
// 128x128 CTA tile, K-chunk 32, 3-stage cp.async pipeline (96KB smem),
// 8 warps (4x2), warp tile 32x64. 2 CTAs/SM.
// Packed smem layout: logical row r at (r&63)*128 + (r>>6)*64 + kbyte.
// ===========================================================================
#define KC2 32
#define KIT2 (DD / KC2)               // 32
#define STAGE_B 32768                 // aHi|aLo|bHi|bLo, 8KB each
#define NSTAGE 3
#define SMEM_GEMM_SZ (NSTAGE * STAGE_B)   // 98304

__device__ __forceinline__ void issue_stage(const __nv_bfloat16* __restrict__ aH,
                                            const __nv_bfloat16* __restrict__ aL,
                                            const __nv_bfloat16* __restrict__ bH,
                                            const __nv_bfloat16* __restrict__ bL,
                                            int row0, int col0, int it,
                                            uint32_t stage_base, int t) {
    const int k0 = it * KC2;
    #pragma unroll
    for (int i = 0; i < 8; i++) {
        const int c   = t + i * 256;          // 0..2047
        const int arr = c >> 9;               // 0..3
        const int r   = (c & 511) >> 2;       // 0..127
        const int kc  = c & 3;                // 16B chunk within row
        const __nv_bfloat16* base;
        int rowg;
        if (arr == 0)      { base = aH; rowg = row0 + r; }
        else if (arr == 1) { base = aL; rowg = row0 + r; }
        else if (arr == 2) { base = bH; rowg = col0 + r; }
        else               { base = bL; rowg = col0 + r; }
        const __nv_bfloat16* src = base + (long)rowg * DD + k0 + kc * 8;
        const uint32_t off = sw128((uint32_t)((r & 63) * 128 + ((r >> 6) << 6) + kc * 16));
        cp_async16(stage_base + arr * 8192 + off, src);
    }
}

__device__ __forceinline__ void gemm_cpasync(const __nv_bfloat16* __restrict__ aH,
                                             const __nv_bfloat16* __restrict__ aL,
                                             const __nv_bfloat16* __restrict__ bH,
                                             const __nv_bfloat16* __restrict__ bL,
                                             float* __restrict__ C,
                                             int row0, int col0) {
    extern __shared__ char smem[];
    const uint32_t sb = smem_u32(smem);
    const int t      = threadIdx.x;
    const int wid    = t >> 5;
    const int lane   = t & 31;
    const int warp_m = wid >> 1;       // 0..3  (32 rows each)
    const int warp_n = wid & 1;        // 0..1  (64 cols each)

    float acc[2][8][4] = {};

    issue_stage(aH, aL, bH, bL, row0, col0, 0, sb, t); CP_COMMIT();
    issue_stage(aH, aL, bH, bL, row0, col0, 1, sb + STAGE_B, t); CP_COMMIT();

    int s = 0;
    for (int it = 0; it < KIT2; it++) {
        if (it == KIT2 - 1) { CP_WAIT(0); } else { CP_WAIT(1); }
        __syncthreads();

        const uint32_t stH = sb + s * STAGE_B;
        const uint32_t stL = stH + 8192;
        const uint32_t sbH = stH + 16384;
        const uint32_t sbL = stH + 24576;

        #pragma unroll
        for (int ks = 0; ks < 2; ks++) {
            uint32_t AH[2][4], AL[2][4];
            #pragma unroll
            for (int mt = 0; mt < 2; mt++) {
                const int row = warp_m * 32 + mt * 16 + (lane & 15);
                const int kb  = ks * 32 + (lane >> 4) * 16;
                const uint32_t off =
                    sw128((uint32_t)((row & 63) * 128 + ((row >> 6) << 6) + kb));
                ldsm_x4(AH[mt], stH + off);
                ldsm_x4(AL[mt], stL + off);
            }
            #pragma unroll
            for (int nt = 0; nt < 8; nt++) {
                const int rowb = warp_n * 64 + nt * 8 + (lane & 7);
                const int kb   = ks * 32 + ((lane >> 3) & 1) * 16;
                const uint32_t off =
                    sw128((uint32_t)((rowb & 63) * 128 + ((rowb >> 6) << 6) + kb));
                uint32_t BH[2], BL[2];
                ldsm_x2(BH, sbH + off);
                ldsm_x2(BL, sbL + off);
                #pragma unroll
                for (int mt = 0; mt < 2; mt++) {
                    mma16816(acc[mt][nt], AH[mt], BH);
                    mma16816(acc[mt][nt], AH[mt], BL);
                    mma16816(acc[mt][nt], AL[mt], BH);
                }
            }
        }

        if (it + 2 < KIT2) {
            const int nx = (it + 2) % NSTAGE;
            issue_stage(aH, aL, bH, bL, row0, col0, it + 2, sb + nx * STAGE_B, t);
            CP_COMMIT();
        }
        s = (s + 1) % NSTAGE;
    }

    const int fg = lane >> 2;
    const int tg = lane & 3;
    #pragma unroll
    for (int mt = 0; mt < 2; mt++) {
        #pragma unroll
        for (int nt = 0; nt < 8; nt++) {
            const long r = row0 + warp_m * 32 + mt * 16 + fg;
            const long c = col0 + warp_n * 64 + nt * 8 + tg * 2;
            *reinterpret_cast<float2*>(&C[r * DD + c]) =
                make_float2(acc[mt][nt][0], acc[mt][nt][1]);
            *reinterpret_cast<float2*>(&C[(r + 8) * DD + c]) =
                make_float2(acc[mt][nt][2], acc[mt][nt][3]);
        }
    }
}

__global__ __launch_bounds__(256, 2)
void gemm_qkv_tc(const __nv_bfloat16* __restrict__ xH,
                 const __nv_bfloat16* __restrict__ xL) {
    const __nv_bfloat16 *bH, *bL;
    float* C;
    if (blockIdx.z == 0)      { bH = g_wqH; bL = g_wqL; C = g_Q; }
    else if (blockIdx.z == 1) { bH = g_wkH; bL = g_wkL; C = g_K; }
    else                      { bH = g_wvH; bL = g_wvL; C = g_V; }
    gemm_cpasync(xH, xL, bH, bL, C, blockIdx.y * 128, blockIdx.x * 128);
}

__global__ __launch_bounds__(256, 2)
void gemm_out_tc(const __nv_bfloat16* __restrict__ aH,
                 const __nv_bfloat16* __restrict__ aL,
                 float* __restrict__ out) {
    gemm_cpasync(aH, aL, g_woH, g_woL, out, blockIdx.y * 128, blockIdx.x * 128);
}

// ---------------------------------------------------------------------------
// RoPE applied in-place to Q and K. Layout: [B, S, H, DK].
// ---------------------------------------------------------------------------
__global__ void rope_kernel(float* __restrict__ Q, float* __restrict__ K,
                            const int* __restrict__ pos) {
    const int idx = blockIdx.x * blockDim.x + threadIdx.x;
    const int i  = idx & 31;
    const int h  = (idx >> 5) & (HH - 1);
    const int bs = idx >> 9;
    const int s  = bs & (SS - 1);

    const float p = (float)pos[s];
    const float inv = exp2f(-(float)i * 0.4152410118607953f);
    const float ang = p * inv;
    float sn, cs;
    sincosf(ang, &sn, &cs);

    const long base = (long)bs * DD + h * DKK + 2 * i;

    float q1 = Q[base], q2 = Q[base + 1];
    Q[base]     = q1 * cs - q2 * sn;
    Q[base + 1] = q1 * sn + q2 * cs;

    float k1 = K[base], k2 = K[base + 1];
    K[base]     = k1 * cs - k2 * sn;
    K[base + 1] = k1 * sn + k2 * cs;
}

// ===========================================================================
// Tensor-core causal flash attention (mma.sync, bf16x3) — unchanged from R13
// ===========================================================================
#define SMEM_ATT 32768

__global__ __launch_bounds__(256)
void attn_mma_kernel(const float* __restrict__ Q,
                     const float* __restrict__ K,
                     const float* __restrict__ V,
                     float* __restrict__ O) {
    __shared__ char sm[SMEM_ATT];
    const uint32_t sb = smem_u32(sm);

    const int t    = threadIdx.x;
    const int w    = t >> 5;
    const int lane = t & 31;
    const int g    = lane >> 2;
    const int tg   = lane & 3;

    const int qi    = gridDim.x - 1 - blockIdx.x;
    const int bh    = blockIdx.y;
    const int b     = bh >> 4;
    const int h     = bh & (HH - 1);
    const int row0g = qi * 128;
    const long rowbase = (long)b * SS;
    const long hoff = h * DKK;

    {
        char* QH = sm;
        char* QL = sm + 16384;
        #pragma unroll
        for (int i = 0; i < 8; i++) {
            const int gidx = t + i * 256;
            const int row = gidx >> 4;
            const int seg = gidx & 15;
            const float4 v4 = *reinterpret_cast<const float4*>(
                Q + (rowbase + row0g + row) * DD + hoff + seg * 4);
            float f[4] = {v4.x * 0.125f, v4.y * 0.125f, v4.z * 0.125f, v4.w * 0.125f};
            float h0 = __bfloat162float(__float2bfloat16_rn(f[0]));
            float h1 = __bfloat162float(__float2bfloat16_rn(f[1]));
            float h2 = __bfloat162float(__float2bfloat16_rn(f[2]));
            float h3 = __bfloat162float(__float2bfloat16_rn(f[3]));
            uint2 hv = make_uint2(pack_bf16x2(h0, h1), pack_bf16x2(h2, h3));
            uint2 lv = make_uint2(pack_bf16x2(f[0] - h0, f[1] - h1),
                                  pack_bf16x2(f[2] - h2, f[3] - h3));
            const uint32_t off = sw128((uint32_t)(row * 128 + seg * 8));
            *reinterpret_cast<uint2*>(QH + off) = hv;
            *reinterpret_cast<uint2*>(QL + off) = lv;
        }
    }
    __syncthreads();

    uint32_t QHf[4][4], QLf[4][4];
    #pragma unroll
    for (int kt = 0; kt < 4; kt++) {
        const int row = w * 16 + (lane & 15);
        const int kb  = kt * 32 + (lane >> 4) * 16;
        const uint32_t off = sw128((uint32_t)(row * 128 + kb));
        ldsm_x4(QHf[kt], sb + off);
        ldsm_x4(QLf[kt], sb + 16384 + off);
    }

    float m0 = -1e30f, m1 = -1e30f, l0 = 0.f, l1 = 0.f;
    float Oacc[8][4] = {};

    const int qbase = row0g + w * 16;
    const int qmax_w = qbase + 15;
    const int kend = row0g + 128;

    const uint32_t KH  = sb;
    const uint32_t KL  = sb + 8192;
    const uint32_t VtH = sb + 16384;
    const uint32_t VtL = sb + 24576;

    for (int j0 = 0; j0 < kend; j0 += 64) {
        __syncthreads();

        #pragma unroll
        for (int i = 0; i < 4; i++) {
            const int gidx = t + i * 256;
            const int row = gidx >> 4;
            const int seg = gidx & 15;
            const float4 v4 = *reinterpret_cast<const float4*>(
                K + (rowbase + j0 + row) * DD + hoff + seg * 4);
            float h0 = __bfloat162float(__float2bfloat16_rn(v4.x));
            float h1 = __bfloat162float(__float2bfloat16_rn(v4.y));
            float h2 = __bfloat162float(__float2bfloat16_rn(v4.z));
            float h3 = __bfloat162float(__float2bfloat16_rn(v4.w));
            const uint32_t off = sw128((uint32_t)(row * 128 + seg * 8));
            *reinterpret_cast<uint2*>(sm + (KH - sb) + off) =
                make_uint2(pack_bf16x2(h0, h1), pack_bf16x2(h2, h3));
            *reinterpret_cast<uint2*>(sm + (KL - sb) + off) =
                make_uint2(pack_bf16x2(v4.x - h0, v4.y - h1),
                           pack_bf16x2(v4.z - h2, v4.w - h3));
        }
        #pragma unroll
        for (int i = 0; i < 2; i++) {
            const int u  = t + i * 256;
            const int dg = u & 15;
            const int kp = u >> 4;
            const float4 v0 = *reinterpret_cast<const float4*>(
                V + (rowbase + j0 + 2 * kp) * DD + hoff + dg * 4);
            const float4 v1 = *reinterpret_cast<const float4*>(
                V + (rowbase + j0 + 2 * kp + 1) * DD + hoff + dg * 4);
            const float a0[4] = {v0.x, v0.y, v0.z, v0.w};
            const float a1[4] = {v1.x, v1.y, v1.z, v1.w};
            #pragma unroll
            for (int jj = 0; jj < 4; jj++) {
                const int d = dg * 4 + jj;
                float h0 = __bfloat162float(__float2bfloat16_rn(a0[jj]));
                float h1 = __bfloat162float(__float2bfloat16_rn(a1[jj]));
                const uint32_t off = sw128((uint32_t)(d * 128 + kp * 4));
                *reinterpret_cast<uint32_t*>(sm + (VtH - sb) + off) = pack_bf16x2(h0, h1);
                *reinterpret_cast<uint32_t*>(sm + (VtL - sb) + off) =
                    pack_bf16x2(a0[jj] - h0, a1[jj] - h1);
            }
        }
        __syncthreads();

        if (j0 > qmax_w) continue;

        float Sacc[8][4] = {};
        #pragma unroll
        for (int nt = 0; nt < 8; nt++) {
            #pragma unroll
            for (int ks = 0; ks < 4; ks++) {
                const int rowb = nt * 8 + (lane & 7);
                const int kb   = ks * 32 + ((lane >> 3) & 1) * 16;
                const uint32_t off = sw128((uint32_t)(rowb * 128 + kb));
                uint32_t BH[2], BL[2];
                ldsm_x2(BH, KH + off);
                ldsm_x2(BL, KL + off);
                mma16816(Sacc[nt], QHf[ks], BH);
                mma16816(Sacc[nt], QHf[ks], BL);
                mma16816(Sacc[nt], QLf[ks], BH);
            }
        }

        const bool need_mask = (j0 + 63 > qbase);
        float rmax0 = -1e30f, rmax1 = -1e30f;
        #pragma unroll
        for (int nt = 0; nt < 8; nt++) {
            if (need_mask) {
                const int c0 = j0 + nt * 8 + tg * 2;
                const int q0 = qbase + g;
                if (c0     > q0)     Sacc[nt][0] = -1e30f;
                if (c0 + 1 > q0)     Sacc[nt][1] = -1e30f;
                if (c0     > q0 + 8) Sacc[nt][2] = -1e30f;
                if (c0 + 1 > q0 + 8) Sacc[nt][3] = -1e30f;
            }
            rmax0 = fmaxf(rmax0, fmaxf(Sacc[nt][0], Sacc[nt][1]));
            rmax1 = fmaxf(rmax1, fmaxf(Sacc[nt][2], Sacc[nt][3]));
        }
        rmax0 = fmaxf(rmax0, __shfl_xor_sync(0xffffffffu, rmax0, 1));
        rmax0 = fmaxf(rmax0, __shfl_xor_sync(0xffffffffu, rmax0, 2));
        rmax1 = fmaxf(rmax1, __shfl_xor_sync(0xffffffffu, rmax1, 1));
        rmax1 = fmaxf(rmax1, __shfl_xor_sync(0xffffffffu, rmax1, 2));

        const float m0n = fmaxf(m0, rmax0);
        const float m1n = fmaxf(m1, rmax1);
        const float corr0 = __expf(m0 - m0n);
        const float corr1 = __expf(m1 - m1n);
        m0 = m0n; m1 = m1n;

        float rsum0 = 0.f, rsum1 = 0.f;
        #pragma unroll
        for (int nt = 0; nt < 8; nt++) {
            Sacc[nt][0] = __expf(Sacc[nt][0] - m0);
            Sacc[nt][1] = __expf(Sacc[nt][1] - m0);
            Sacc[nt][2] = __expf(Sacc[nt][2] - m1);
            Sacc[nt][3] = __expf(Sacc[nt][3] - m1);
            rsum0 += Sacc[nt][0] + Sacc[nt][1];
            rsum1 += Sacc[nt][2] + Sacc[nt][3];
        }
        rsum0 += __shfl_xor_sync(0xffffffffu, rsum0, 1);
        rsum0 += __shfl_xor_sync(0xffffffffu, rsum0, 2);
        rsum1 += __shfl_xor_sync(0xffffffffu, rsum1, 1);
        rsum1 += __shfl_xor_sync(0xffffffffu, rsum1, 2);
        l0 = l0 * corr0 + rsum0;
        l1 = l1 * corr1 + rsum1;

        #pragma unroll
        for (int nt = 0; nt < 8; nt++) {
            Oacc[nt][0] *= corr0;
            Oacc[nt][1] *= corr0;
            Oacc[nt][2] *= corr1;
            Oacc[nt][3] *= corr1;
        }

        uint32_t PH[4][4], PL[4][4];
        #pragma unroll
        for (int ks = 0; ks < 4; ks++) {
            #pragma unroll
            for (int half = 0; half < 2; half++) {
                const float* S = Sacc[2 * ks + half];
                float h0 = __bfloat162float(__float2bfloat16_rn(S[0]));
                float h1 = __bfloat162float(__float2bfloat16_rn(S[1]));
                float h2 = __bfloat162float(__float2bfloat16_rn(S[2]));
                float h3 = __bfloat162float(__float2bfloat16_rn(S[3]));
                PH[ks][2 * half + 0] = pack_bf16x2(h0, h1);
                PH[ks][2 * half + 1] = pack_bf16x2(h2, h3);
                PL[ks][2 * half + 0] = pack_bf16x2(S[0] - h0, S[1] - h1);
                PL[ks][2 * half + 1] = pack_bf16x2(S[2] - h2, S[3] - h3);
            }
        }

        #pragma unroll
        for (int nt = 0; nt < 8; nt++) {
            #pragma unroll
            for (int ks = 0; ks < 4; ks++) {
                const int rowb = nt * 8 + (lane & 7);
                const int kb   = ks * 32 + ((lane >> 3) & 1) * 16;
                const uint32_t off = sw128((uint32_t)(rowb * 128 + kb));
                uint32_t VHf[2], VLf[2];
                ldsm_x2(VHf, VtH + off);
                ldsm_x2(VLf, VtL + off);
                mma16816(Oacc[nt], PH[ks], VHf);
                mma16816(Oacc[nt], PH[ks], VLf);
                mma16816(Oacc[nt], PL[ks], VHf);
            }
        }
    }

    const float inv0 = 1.f / l0;
    const float inv1 = 1.f / l1;
    #pragma unroll
    for (int nt = 0; nt < 8; nt++) {
        const long r0 = rowbase + qbase + g;
        const long c  = hoff + nt * 8 + tg * 2;
        *reinterpret_cast<float2*>(&O[r0 * DD + c]) =
            make_float2(Oacc[nt][0] * inv0, Oacc[nt][1] * inv0);
        *reinterpret_cast<float2*>(&O[(r0 + 8) * DD + c]) =
            make_float2(Oacc[nt][2] * inv1, Oacc[nt][3] * inv1);
    }
}

// ---------------------------------------------------------------------------
// Launch
// ---------------------------------------------------------------------------
extern "C" void kernel_launch(void* const* d_in, const int* in_sizes, int n_in,
                              void* d_out, int out_size) {
    const float* x   = (const float*)d_in[0];
    const int*   tp  = (const int*)  d_in[1];
    const float* Wq  = (const float*)d_in[2];
    const float* Wk  = (const float*)d_in[3];
    const float* Wv  = (const float*)d_in[4];
    const float* Wo  = (const float*)d_in[5];
    float* out = (float*)d_out;

    float *gQ, *gK, *gV, *gAO;
    cudaGetSymbolAddress((void**)&gQ,  g_Q);
    cudaGetSymbolAddress((void**)&gK,  g_K);
    cudaGetSymbolAddress((void**)&gV,  g_V);
    cudaGetSymbolAddress((void**)&gAO, g_AO);

    __nv_bfloat16 *xH, *xL, *aoH, *aoL;
    __nv_bfloat16 *wqH, *wqL, *wkH, *wkL, *wvH, *wvL, *woH, *woL;
    cudaGetSymbolAddress((void**)&xH,  g_xH);
    cudaGetSymbolAddress((void**)&xL,  g_xL);
    cudaGetSymbolAddress((void**)&aoH, g_aoH);
    cudaGetSymbolAddress((void**)&aoL, g_aoL);
    cudaGetSymbolAddress((void**)&wqH, g_wqH);
    cudaGetSymbolAddress((void**)&wqL, g_wqL);
    cudaGetSymbolAddress((void**)&wkH, g_wkH);
    cudaGetSymbolAddress((void**)&wkL, g_wkL);
    cudaGetSymbolAddress((void**)&wvH, g_wvH);
    cudaGetSymbolAddress((void**)&wvL, g_wvL);
    cudaGetSymbolAddress((void**)&woH, g_woH);
    cudaGetSymbolAddress((void**)&woL, g_woL);

    cudaFuncSetAttribute(gemm_qkv_tc, cudaFuncAttributeMaxDynamicSharedMemorySize,
                         SMEM_GEMM_SZ);
    cudaFuncSetAttribute(gemm_out_tc, cudaFuncAttributeMaxDynamicSharedMemorySize,
                         SMEM_GEMM_SZ);

    // Pre-split operands to bf16 hi/lo
    split_kernel<<<MS * DD / 4 / 256, 256>>>(x, xH, xL);
    split_kernel<<<DD * DD / 4 / 256, 256>>>(Wq, wqH, wqL);
    split_kernel<<<DD * DD / 4 / 256, 256>>>(Wk, wkH, wkL);
    split_kernel<<<DD * DD / 4 / 256, 256>>>(Wv, wvH, wvL);
    split_kernel<<<DD * DD / 4 / 256, 256>>>(Wo, woH, woL);

    // QKV projections
    {
        dim3 grid(DD / 128, MS / 128, 3);
        gemm_qkv_tc<<<grid, 256, SMEM_GEMM_SZ>>>(xH, xL);
    }

    // RoPE on Q and K
    {
        int total_pairs = MS * DD / 2;
        rope_kernel<<<total_pairs / 256, 256>>>(gQ, gK, tp);
    }

    // Causal flash attention (mma.sync bf16x3)
    {
        dim3 agrid(SS / 128, BB * HH);
        attn_mma_kernel<<<agrid, 256>>>(gQ, gK, gV, gAO);
    }

    // Split attention output, then output projection
    split_kernel<<<MS * DD / 4 / 256, 256>>>(gAO, aoH, aoL);
    {
        dim3 grid(DD / 128, MS / 128);
        gemm_out_tc<<<grid, 256, SMEM_GEMM_SZ>>>(aoH, aoL, out);
    }
}

// round 16
// speedup vs baseline: 3.6969x; 1.2085x over previous
#include <cuda_runtime.h>
#include <cuda_bf16.h>
#include <math.h>
#include <stdint.h>

// Problem constants
#define BB 4
#define SS 2048
#define DD 1024
#define HH 16
#define DKK 64
#define MS (BB*SS)          // 8192 rows

// Scratch (static device arrays — no allocation at runtime)
__device__ float g_Q[MS*DD];
__device__ float g_K[MS*DD];
__device__ float g_V[MS*DD];

// Pre-split bf16 hi/lo operands
__device__ __nv_bfloat16 g_xH[MS*DD],  g_xL[MS*DD];
__device__ __nv_bfloat16 g_aoH[MS*DD], g_aoL[MS*DD];
__device__ __nv_bfloat16 g_wqH[DD*DD], g_wqL[DD*DD];
__device__ __nv_bfloat16 g_wkH[DD*DD], g_wkL[DD*DD];
__device__ __nv_bfloat16 g_wvH[DD*DD], g_wvL[DD*DD];
__device__ __nv_bfloat16 g_woH[DD*DD], g_woL[DD*DD];
// Attention operands (bf16 hi/lo); q scaled by 1/8, vt in [B,H,DK,S]
__device__ __nv_bfloat16 g_qH[MS*DD],  g_qL[MS*DD];
__device__ __nv_bfloat16 g_kH[MS*DD],  g_kL[MS*DD];
__device__ __nv_bfloat16 g_vtH[MS*DD], g_vtL[MS*DD];

// ===========================================================================
// Helpers
// ===========================================================================
__device__ __forceinline__ uint32_t smem_u32(const void* p) {
    uint32_t a;
    asm("{ .reg .u64 t; cvta.to.shared.u64 t, %1; cvt.u32.u64 %0, t; }"
        : "=r"(a) : "l"(p));
    return a;
}

__device__ __forceinline__ uint32_t sw128(uint32_t off) {
    return off ^ ((off >> 3) & 0x70);
}

__device__ __forceinline__ void ldsm_x4(uint32_t* r, uint32_t addr) {
    asm volatile("ldmatrix.sync.aligned.m8n8.x4.shared.b16 {%0,%1,%2,%3}, [%4];"
                 : "=r"(r[0]), "=r"(r[1]), "=r"(r[2]), "=r"(r[3]) : "r"(addr));
}

__device__ __forceinline__ void ldsm_x2(uint32_t* r, uint32_t addr) {
    asm volatile("ldmatrix.sync.aligned.m8n8.x2.shared.b16 {%0,%1}, [%2];"
                 : "=r"(r[0]), "=r"(r[1]) : "r"(addr));
}

__device__ __forceinline__ void mma16816(float* c, const uint32_t* a, const uint32_t* b) {
    asm volatile(
        "mma.sync.aligned.m16n8k16.row.col.f32.bf16.bf16.f32 "
        "{%0,%1,%2,%3}, {%4,%5,%6,%7}, {%8,%9}, {%0,%1,%2,%3};"
        : "+f"(c[0]), "+f"(c[1]), "+f"(c[2]), "+f"(c[3])
        : "r"(a[0]), "r"(a[1]), "r"(a[2]), "r"(a[3]), "r"(b[0]), "r"(b[1]));
}

__device__ __forceinline__ uint32_t pack_bf16x2(float a, float b) {
    __nv_bfloat162 h = __floats2bfloat162_rn(a, b);
    return *reinterpret_cast<uint32_t*>(&h);
}

__device__ __forceinline__ void cp_async16(uint32_t dst, const void* src) {
    asm volatile("cp.async.cg.shared.global [%0], [%1], 16;"
                 :: "r"(dst), "l"(src));
}
#define CP_COMMIT() asm volatile("cp.async.commit_group;" ::: "memory")
#define CP_WAIT(n)  asm volatile("cp.async.wait_group %0;" :: "n"(n) : "memory")

// ===========================================================================
// Split pass: fp32 -> (bf16 hi, bf16 lo) elementwise, float4-vectorized
// ===========================================================================
__global__ __launch_bounds__(256)
void split_kernel(const float* __restrict__ src,
                  __nv_bfloat16* __restrict__ hi,
                  __nv_bfloat16* __restrict__ lo) {
    const int idx = blockIdx.x * blockDim.x + threadIdx.x;
    const float4 v = reinterpret_cast<const float4*>(src)[idx];
    const float f[4] = {v.x, v.y, v.z, v.w};
    float h[4];
    #pragma unroll
    for (int j = 0; j < 4; j++)
        h[j] = __bfloat162float(__float2bfloat16_rn(f[j]));
    reinterpret_cast<uint2*>(hi)[idx] =
        make_uint2(pack_bf16x2(h[0], h[1]), pack_bf16x2(h[2], h[3]));
    reinterpret_cast<uint2*>(lo)[idx] =
        make_uint2(pack_bf16x2(f[0] - h[0], f[1] - h[1]),
                   pack_bf16x2(f[2] - h[2], f[3] - h[3]));
}

// ===========================================================================
// cp.async tensor-core GEMM (unchanged from R15)
// ===========================================================================
#define KC2 32
#define KIT2 (DD / KC2)               // 32
#define STAGE_B 32768
#define NSTAGE 3
#define SMEM_GEMM_SZ (NSTAGE * STAGE_B)

__device__ __forceinline__ void issue_stage(const __nv_bfloat16* __restrict__ aH,
                                            const __nv_bfloat16* __restrict__ aL,
                                            const __nv_bfloat16* __restrict__ bH,
                                            const __nv_bfloat16* __restrict__ bL,
                                            int row0, int col0, int it,
                                            uint32_t stage_base, int t) {
    const int k0 = it * KC2;
    #pragma unroll
    for (int i = 0; i < 8; i++) {
        const int c   = t + i * 256;
        const int arr = c >> 9;
        const int r   = (c & 511) >> 2;
        const int kc  = c & 3;
        const __nv_bfloat16* base;
        int rowg;
        if (arr == 0)      { base = aH; rowg = row0 + r; }
        else if (arr == 1) { base = aL; rowg = row0 + r; }
        else if (arr == 2) { base = bH; rowg = col0 + r; }
        else               { base = bL; rowg = col0 + r; }
        const __nv_bfloat16* src = base + (long)rowg * DD + k0 + kc * 8;
        const uint32_t off = sw128((uint32_t)((r & 63) * 128 + ((r >> 6) << 6) + kc * 16));
        cp_async16(stage_base + arr * 8192 + off, src);
    }
}

__device__ __forceinline__ void gemm_cpasync(const __nv_bfloat16* __restrict__ aH,
                                             const __nv_bfloat16* __restrict__ aL,
                                             const __nv_bfloat16* __restrict__ bH,
                                             const __nv_bfloat16* __restrict__ bL,
                                             float* __restrict__ C,
                                             int row0, int col0) {
    extern __shared__ char smem[];
    const uint32_t sb = smem_u32(smem);
    const int t      = threadIdx.x;
    const int wid    = t >> 5;
    const int lane   = t & 31;
    const int warp_m = wid >> 1;
    const int warp_n = wid & 1;

    float acc[2][8][4] = {};

    issue_stage(aH, aL, bH, bL, row0, col0, 0, sb, t); CP_COMMIT();
    issue_stage(aH, aL, bH, bL, row0, col0, 1, sb + STAGE_B, t); CP_COMMIT();

    int s = 0;
    for (int it = 0; it < KIT2; it++) {
        if (it == KIT2 - 1) { CP_WAIT(0); } else { CP_WAIT(1); }
        __syncthreads();

        const uint32_t stH = sb + s * STAGE_B;
        const uint32_t stL = stH + 8192;
        const uint32_t sbH = stH + 16384;
        const uint32_t sbL = stH + 24576;

        #pragma unroll
        for (int ks = 0; ks < 2; ks++) {
            uint32_t AH[2][4], AL[2][4];
            #pragma unroll
            for (int mt = 0; mt < 2; mt++) {
                const int row = warp_m * 32 + mt * 16 + (lane & 15);
                const int kb  = ks * 32 + (lane >> 4) * 16;
                const uint32_t off =
                    sw128((uint32_t)((row & 63) * 128 + ((row >> 6) << 6) + kb));
                ldsm_x4(AH[mt], stH + off);
                ldsm_x4(AL[mt], stL + off);
            }
            #pragma unroll
            for (int nt = 0; nt < 8; nt++) {
                const int rowb = warp_n * 64 + nt * 8 + (lane & 7);
                const int kb   = ks * 32 + ((lane >> 3) & 1) * 16;
                const uint32_t off =
                    sw128((uint32_t)((rowb & 63) * 128 + ((rowb >> 6) << 6) + kb));
                uint32_t BH[2], BL[2];
                ldsm_x2(BH, sbH + off);
                ldsm_x2(BL, sbL + off);
                #pragma unroll
                for (int mt = 0; mt < 2; mt++) {
                    mma16816(acc[mt][nt], AH[mt], BH);
                    mma16816(acc[mt][nt], AH[mt], BL);
                    mma16816(acc[mt][nt], AL[mt], BH);
                }
            }
        }

        if (it + 2 < KIT2) {
            const int nx = (it + 2) % NSTAGE;
            issue_stage(aH, aL, bH, bL, row0, col0, it + 2, sb + nx * STAGE_B, t);
            CP_COMMIT();
        }
        s = (s + 1) % NSTAGE;
    }

    const int fg = lane >> 2;
    const int tg = lane & 3;
    #pragma unroll
    for (int mt = 0; mt < 2; mt++) {
        #pragma unroll
        for (int nt = 0; nt < 8; nt++) {
            const long r = row0 + warp_m * 32 + mt * 16 + fg;
            const long c = col0 + warp_n * 64 + nt * 8 + tg * 2;
            *reinterpret_cast<float2*>(&C[r * DD + c]) =
                make_float2(acc[mt][nt][0], acc[mt][nt][1]);
            *reinterpret_cast<float2*>(&C[(r + 8) * DD + c]) =
                make_float2(acc[mt][nt][2], acc[mt][nt][3]);
        }
    }
}

__global__ __launch_bounds__(256, 2)
void gemm_qkv_tc(const __nv_bfloat16* __restrict__ xH,
                 const __nv_bfloat16* __restrict__ xL) {
    const __nv_bfloat16 *bH, *bL;
    float* C;
    if (blockIdx.z == 0)      { bH = g_wqH; bL = g_wqL; C = g_Q; }
    else if (blockIdx.z == 1) { bH = g_wkH; bL = g_wkL; C = g_K; }
    else                      { bH = g_wvH; bL = g_wvL; C = g_V; }
    gemm_cpasync(xH, xL, bH, bL, C, blockIdx.y * 128, blockIdx.x * 128);
}

__global__ __launch_bounds__(256, 2)
void gemm_out_tc(const __nv_bfloat16* __restrict__ aH,
                 const __nv_bfloat16* __restrict__ aL,
                 float* __restrict__ out) {
    gemm_cpasync(aH, aL, g_woH, g_woL, out, blockIdx.y * 128, blockIdx.x * 128);
}

// ---------------------------------------------------------------------------
// Fused RoPE + hi/lo split.  Reads fp32 Q/K, writes bf16 hi/lo arrays.
// Q gets the 1/sqrt(64) scale folded in.
// ---------------------------------------------------------------------------
__global__ void rope_split_kernel(const float* __restrict__ Q,
                                  const float* __restrict__ K,
                                  const int* __restrict__ pos) {
    const int idx = blockIdx.x * blockDim.x + threadIdx.x;
    const int i  = idx & 31;
    const int h  = (idx >> 5) & (HH - 1);
    const int bs = idx >> 9;
    const int s  = bs & (SS - 1);

    const float p = (float)pos[s];
    const float inv = exp2f(-(float)i * 0.4152410118607953f);
    const float ang = p * inv;
    float sn, cs;
    sincosf(ang, &sn, &cs);

    const long base = (long)bs * DD + h * DKK + 2 * i;

    {
        const float q1 = Q[base], q2 = Q[base + 1];
        const float r1 = (q1 * cs - q2 * sn) * 0.125f;
        const float r2 = (q1 * sn + q2 * cs) * 0.125f;
        const float h1 = __bfloat162float(__float2bfloat16_rn(r1));
        const float h2 = __bfloat162float(__float2bfloat16_rn(r2));
        *reinterpret_cast<uint32_t*>(&g_qH[base]) = pack_bf16x2(h1, h2);
        *reinterpret_cast<uint32_t*>(&g_qL[base]) = pack_bf16x2(r1 - h1, r2 - h2);
    }
    {
        const float k1 = K[base], k2 = K[base + 1];
        const float r1 = k1 * cs - k2 * sn;
        const float r2 = k1 * sn + k2 * cs;
        const float h1 = __bfloat162float(__float2bfloat16_rn(r1));
        const float h2 = __bfloat162float(__float2bfloat16_rn(r2));
        *reinterpret_cast<uint32_t*>(&g_kH[base]) = pack_bf16x2(h1, h2);
        *reinterpret_cast<uint32_t*>(&g_kL[base]) = pack_bf16x2(r1 - h1, r2 - h2);
    }
}

// ---------------------------------------------------------------------------
// V transpose + split:  V[b,s,h,dk] fp32  ->  vt[b,h,dk,s] bf16 hi/lo
// ---------------------------------------------------------------------------
__global__ __launch_bounds__(256)
void vt_split_kernel(const float* __restrict__ V) {
    __shared__ float Vs[64][65];
    const int t  = threadIdx.x;
    const int j0 = blockIdx.x * 64;
    const int bh = blockIdx.y;
    const int b  = bh >> 4;
    const int h  = bh & (HH - 1);

    {
        const int r = t >> 2;
        const int c0 = (t & 3) * 16;
        const float* src = V + ((long)(b * SS + j0 + r)) * DD + h * DKK + c0;
        #pragma unroll
        for (int i = 0; i < 4; i++) {
            const float4 v = *reinterpret_cast<const float4*>(src + i * 4);
            Vs[r][c0 + i * 4 + 0] = v.x;
            Vs[r][c0 + i * 4 + 1] = v.y;
            Vs[r][c0 + i * 4 + 2] = v.z;
            Vs[r][c0 + i * 4 + 3] = v.w;
        }
    }
    __syncthreads();

    const int c  = t >> 2;            // dk row 0..63
    const int kq = (t & 3) * 16;      // 16 keys
    uint32_t hi[8], lo[8];
    #pragma unroll
    for (int j = 0; j < 8; j++) {
        const float a = Vs[kq + 2 * j][c];
        const float d = Vs[kq + 2 * j + 1][c];
        const float ha = __bfloat162float(__float2bfloat16_rn(a));
        const float hd = __bfloat162float(__float2bfloat16_rn(d));
        hi[j] = pack_bf16x2(ha, hd);
        lo[j] = pack_bf16x2(a - ha, d - hd);
    }
    const long off = ((long)bh * DKK + c) * SS + j0 + kq;
    *reinterpret_cast<uint4*>(&g_vtH[off])     = make_uint4(hi[0], hi[1], hi[2], hi[3]);
    *reinterpret_cast<uint4*>(&g_vtH[off + 8]) = make_uint4(hi[4], hi[5], hi[6], hi[7]);
    *reinterpret_cast<uint4*>(&g_vtL[off])     = make_uint4(lo[0], lo[1], lo[2], lo[3]);
    *reinterpret_cast<uint4*>(&g_vtL[off + 8]) = make_uint4(lo[4], lo[5], lo[6], lo[7]);
}

// ===========================================================================
// Tensor-core causal flash attention, pre-split operands + cp.async pipeline.
// 2 stages x 32KB: [KH|KL|VtH|VtL] each 8KB (64 rows x 128B SW128).
// ===========================================================================
#define ATT_STG 32768
#define SMEM_ATT (2 * ATT_STG)

__device__ __forceinline__ void issue_att_tile(const __nv_bfloat16* __restrict__ kH,
                                               const __nv_bfloat16* __restrict__ kL,
                                               const __nv_bfloat16* __restrict__ vtH,
                                               const __nv_bfloat16* __restrict__ vtL,
                                               long rowbase, long hoff, long vtrow0,
                                               int j0, uint32_t stage_base, int t) {
    #pragma unroll
    for (int i = 0; i < 8; i++) {
        const int c   = t + i * 256;          // 0..2047
        const int arr = c >> 9;               // 0:KH 1:KL 2:VtH 3:VtL
        const int r   = (c & 511) >> 3;       // 0..63
        const int ch  = c & 7;
        const __nv_bfloat16* src;
        if (arr == 0)      src = kH  + (rowbase + j0 + r) * DD + hoff + ch * 8;
        else if (arr == 1) src = kL  + (rowbase + j0 + r) * DD + hoff + ch * 8;
        else if (arr == 2) src = vtH + (vtrow0 + r) * SS + j0 + ch * 8;
        else               src = vtL + (vtrow0 + r) * SS + j0 + ch * 8;
        cp_async16(stage_base + arr * 8192 + sw128((uint32_t)(r * 128 + ch * 16)), src);
    }
}

__global__ __launch_bounds__(256)
void attn_mma_kernel(const __nv_bfloat16* __restrict__ qH,
                     const __nv_bfloat16* __restrict__ qL,
                     const __nv_bfloat16* __restrict__ kH,
                     const __nv_bfloat16* __restrict__ kL,
                     const __nv_bfloat16* __restrict__ vtH,
                     const __nv_bfloat16* __restrict__ vtL,
                     __nv_bfloat16* __restrict__ OH,
                     __nv_bfloat16* __restrict__ OL) {
    __shared__ char sm[SMEM_ATT];
    const uint32_t sb = smem_u32(sm);

    const int t    = threadIdx.x;
    const int w    = t >> 5;
    const int lane = t & 31;
    const int g    = lane >> 2;
    const int tg   = lane & 3;

    const int qi    = gridDim.x - 1 - blockIdx.x;   // heavy tiles first
    const int bh    = blockIdx.y;
    const int b     = bh >> 4;
    const int h     = bh & (HH - 1);
    const int row0g = qi * 128;
    const long rowbase = (long)b * SS;
    const long hoff    = (long)h * DKK;
    const long vtrow0  = (long)bh * DKK;

    // ---- Stage Q (128 rows x 128B, hi then lo) via cp.async into stage 0+1
    #pragma unroll
    for (int i = 0; i < 8; i++) {
        const int c     = t + i * 256;        // 0..2047
        const int which = c >> 10;            // 0: hi, 1: lo
        const int r     = (c & 1023) >> 3;    // 0..127
        const int ch    = c & 7;
        const __nv_bfloat16* src =
            (which ? qL : qH) + (rowbase + row0g + r) * DD + hoff + ch * 8;
        cp_async16(sb + which * 16384 + sw128((uint32_t)(r * 128 + ch * 16)), src);
    }
    CP_COMMIT();
    CP_WAIT(0);
    __syncthreads();

    uint32_t QHf[4][4], QLf[4][4];
    #pragma unroll
    for (int kt = 0; kt < 4; kt++) {
        const int row = w * 16 + (lane & 15);
        const int kb  = kt * 32 + (lane >> 4) * 16;
        const uint32_t off = sw128((uint32_t)(row * 128 + kb));
        ldsm_x4(QHf[kt], sb + off);
        ldsm_x4(QLf[kt], sb + 16384 + off);
    }
    __syncthreads();   // Q fragments in regs; smem reusable

    float m0 = -1e30f, m1 = -1e30f, l0 = 0.f, l1 = 0.f;
    float Oacc[8][4] = {};

    const int qbase  = row0g + w * 16;
    const int qmax_w = qbase + 15;
    const int ntiles = (row0g + 128) / 64;

    issue_att_tile(kH, kL, vtH, vtL, rowbase, hoff, vtrow0, 0, sb, t);
    CP_COMMIT();

    for (int ti = 0; ti < ntiles; ti++) {
        const int j0 = ti * 64;
        if (ti + 1 < ntiles) {
            issue_att_tile(kH, kL, vtH, vtL, rowbase, hoff, vtrow0,
                           j0 + 64, sb + ((ti + 1) & 1) * ATT_STG, t);
            CP_COMMIT();
            CP_WAIT(1);
        } else {
            CP_WAIT(0);
        }
        __syncthreads();

        if (j0 <= qmax_w) {
            const uint32_t st  = sb + (ti & 1) * ATT_STG;
            const uint32_t KHs = st;
            const uint32_t KLs = st + 8192;
            const uint32_t VHs = st + 16384;
            const uint32_t VLs = st + 24576;

            // ---- S = Q K^T  (16 x 64), bf16x3
            float Sacc[8][4] = {};
            #pragma unroll
            for (int nt = 0; nt < 8; nt++) {
                #pragma unroll
                for (int ks = 0; ks < 4; ks++) {
                    const int rowb = nt * 8 + (lane & 7);
                    const int kb   = ks * 32 + ((lane >> 3) & 1) * 16;
                    const uint32_t off = sw128((uint32_t)(rowb * 128 + kb));
                    uint32_t BH[2], BL[2];
                    ldsm_x2(BH, KHs + off);
                    ldsm_x2(BL, KLs + off);
                    mma16816(Sacc[nt], QHf[ks], BH);
                    mma16816(Sacc[nt], QHf[ks], BL);
                    mma16816(Sacc[nt], QLf[ks], BH);
                }
            }

            // ---- Mask + online softmax
            const bool need_mask = (j0 + 63 > qbase);
            float rmax0 = -1e30f, rmax1 = -1e30f;
            #pragma unroll
            for (int nt = 0; nt < 8; nt++) {
                if (need_mask) {
                    const int c0 = j0 + nt * 8 + tg * 2;
                    const int q0 = qbase + g;
                    if (c0     > q0)     Sacc[nt][0] = -1e30f;
                    if (c0 + 1 > q0)     Sacc[nt][1] = -1e30f;
                    if (c0     > q0 + 8) Sacc[nt][2] = -1e30f;
                    if (c0 + 1 > q0 + 8) Sacc[nt][3] = -1e30f;
                }
                rmax0 = fmaxf(rmax0, fmaxf(Sacc[nt][0], Sacc[nt][1]));
                rmax1 = fmaxf(rmax1, fmaxf(Sacc[nt][2], Sacc[nt][3]));
            }
            rmax0 = fmaxf(rmax0, __shfl_xor_sync(0xffffffffu, rmax0, 1));
            rmax0 = fmaxf(rmax0, __shfl_xor_sync(0xffffffffu, rmax0, 2));
            rmax1 = fmaxf(rmax1, __shfl_xor_sync(0xffffffffu, rmax1, 1));
            rmax1 = fmaxf(rmax1, __shfl_xor_sync(0xffffffffu, rmax1, 2));

            const float m0n = fmaxf(m0, rmax0);
            const float m1n = fmaxf(m1, rmax1);
            const float corr0 = __expf(m0 - m0n);
            const float corr1 = __expf(m1 - m1n);
            m0 = m0n; m1 = m1n;

            float rsum0 = 0.f, rsum1 = 0.f;
            #pragma unroll
            for (int nt = 0; nt < 8; nt++) {
                Sacc[nt][0] = __expf(Sacc[nt][0] - m0);
                Sacc[nt][1] = __expf(Sacc[nt][1] - m0);
                Sacc[nt][2] = __expf(Sacc[nt][2] - m1);
                Sacc[nt][3] = __expf(Sacc[nt][3] - m1);
                rsum0 += Sacc[nt][0] + Sacc[nt][1];
                rsum1 += Sacc[nt][2] + Sacc[nt][3];
            }
            rsum0 += __shfl_xor_sync(0xffffffffu, rsum0, 1);
            rsum0 += __shfl_xor_sync(0xffffffffu, rsum0, 2);
            rsum1 += __shfl_xor_sync(0xffffffffu, rsum1, 1);
            rsum1 += __shfl_xor_sync(0xffffffffu, rsum1, 2);
            l0 = l0 * corr0 + rsum0;
            l1 = l1 * corr1 + rsum1;

            #pragma unroll
            for (int nt = 0; nt < 8; nt++) {
                Oacc[nt][0] *= corr0;
                Oacc[nt][1] *= corr0;
                Oacc[nt][2] *= corr1;
                Oacc[nt][3] *= corr1;
            }

            // ---- P fragments (hi/lo)
            uint32_t PH[4][4], PL[4][4];
            #pragma unroll
            for (int ks = 0; ks < 4; ks++) {
                #pragma unroll
                for (int half = 0; half < 2; half++) {
                    const float* S = Sacc[2 * ks + half];
                    float h0 = __bfloat162float(__float2bfloat16_rn(S[0]));
                    float h1 = __bfloat162float(__float2bfloat16_rn(S[1]));
                    float h2 = __bfloat162float(__float2bfloat16_rn(S[2]));
                    float h3 = __bfloat162float(__float2bfloat16_rn(S[3]));
                    PH[ks][2 * half + 0] = pack_bf16x2(h0, h1);
                    PH[ks][2 * half + 1] = pack_bf16x2(h2, h3);
                    PL[ks][2 * half + 0] = pack_bf16x2(S[0] - h0, S[1] - h1);
                    PL[ks][2 * half + 1] = pack_bf16x2(S[2] - h2, S[3] - h3);
                }
            }

            // ---- O += P V   (16 x 64), bf16x3
            #pragma unroll
            for (int nt = 0; nt < 8; nt++) {
                #pragma unroll
                for (int ks = 0; ks < 4; ks++) {
                    const int rowb = nt * 8 + (lane & 7);
                    const int kb   = ks * 32 + ((lane >> 3) & 1) * 16;
                    const uint32_t off = sw128((uint32_t)(rowb * 128 + kb));
                    uint32_t VHf[2], VLf[2];
                    ldsm_x2(VHf, VHs + off);
                    ldsm_x2(VLf, VLs + off);
                    mma16816(Oacc[nt], PH[ks], VHf);
                    mma16816(Oacc[nt], PH[ks], VLf);
                    mma16816(Oacc[nt], PL[ks], VHf);
                }
            }
        }

        __syncthreads();
    }

    // ---- Epilogue: write bf16 hi/lo directly (feeds out-projection)
    const float inv0 = 1.f / l0;
    const float inv1 = 1.f / l1;
    #pragma unroll
    for (int nt = 0; nt < 8; nt++) {
        const long r0 = rowbase + qbase + g;
        const long c  = hoff + nt * 8 + tg * 2;
        {
            const float o0 = Oacc[nt][0] * inv0, o1 = Oacc[nt][1] * inv0;
            const float h0 = __bfloat162float(__float2bfloat16_rn(o0));
            const float h1 = __bfloat162float(__float2bfloat16_rn(o1));
            *reinterpret_cast<uint32_t*>(&OH[r0 * DD + c]) = pack_bf16x2(h0, h1);
            *reinterpret_cast<uint32_t*>(&OL[r0 * DD + c]) = pack_bf16x2(o0 - h0, o1 - h1);
        }
        {
            const float o0 = Oacc[nt][2] * inv1, o1 = Oacc[nt][3] * inv1;
            const float h0 = __bfloat162float(__float2bfloat16_rn(o0));
            const float h1 = __bfloat162float(__float2bfloat16_rn(o1));
            *reinterpret_cast<uint32_t*>(&OH[(r0 + 8) * DD + c]) = pack_bf16x2(h0, h1);
            *reinterpret_cast<uint32_t*>(&OL[(r0 + 8) * DD + c]) = pack_bf16x2(o0 - h0, o1 - h1);
        }
    }
}

// ---------------------------------------------------------------------------
// Launch
// ---------------------------------------------------------------------------
extern "C" void kernel_launch(void* const* d_in, const int* in_sizes, int n_in,
                              void* d_out, int out_size) {
    const float* x   = (const float*)d_in[0];
    const int*   tp  = (const int*)  d_in[1];
    const float* Wq  = (const float*)d_in[2];
    const float* Wk  = (const float*)d_in[3];
    const float* Wv  = (const float*)d_in[4];
    const float* Wo  = (const float*)d_in[5];
    float* out = (float*)d_out;

    float *gQ, *gK, *gV;
    cudaGetSymbolAddress((void**)&gQ,  g_Q);
    cudaGetSymbolAddress((void**)&gK,  g_K);
    cudaGetSymbolAddress((void**)&gV,  g_V);

    __nv_bfloat16 *xH, *xL, *aoH, *aoL;
    __nv_bfloat16 *wqH, *wqL, *wkH, *wkL, *wvH, *wvL, *woH, *woL;
    __nv_bfloat16 *qH, *qL, *kHp, *kLp, *vtH, *vtL;
    cudaGetSymbolAddress((void**)&xH,  g_xH);
    cudaGetSymbolAddress((void**)&xL,  g_xL);
    cudaGetSymbolAddress((void**)&aoH, g_aoH);
    cudaGetSymbolAddress((void**)&aoL, g_aoL);
    cudaGetSymbolAddress((void**)&wqH, g_wqH);
    cudaGetSymbolAddress((void**)&wqL, g_wqL);
    cudaGetSymbolAddress((void**)&wkH, g_wkH);
    cudaGetSymbolAddress((void**)&wkL, g_wkL);
    cudaGetSymbolAddress((void**)&wvH, g_wvH);
    cudaGetSymbolAddress((void**)&wvL, g_wvL);
    cudaGetSymbolAddress((void**)&woH, g_woH);
    cudaGetSymbolAddress((void**)&woL, g_woL);
    cudaGetSymbolAddress((void**)&qH,  g_qH);
    cudaGetSymbolAddress((void**)&qL,  g_qL);
    cudaGetSymbolAddress((void**)&kHp, g_kH);
    cudaGetSymbolAddress((void**)&kLp, g_kL);
    cudaGetSymbolAddress((void**)&vtH, g_vtH);
    cudaGetSymbolAddress((void**)&vtL, g_vtL);

    cudaFuncSetAttribute(gemm_qkv_tc, cudaFuncAttributeMaxDynamicSharedMemorySize,
                         SMEM_GEMM_SZ);
    cudaFuncSetAttribute(gemm_out_tc, cudaFuncAttributeMaxDynamicSharedMemorySize,
                         SMEM_GEMM_SZ);

    // Pre-split operands to bf16 hi/lo
    split_kernel<<<MS * DD / 4 / 256, 256>>>(x, xH, xL);
    split_kernel<<<DD * DD / 4 / 256, 256>>>(Wq, wqH, wqL);
    split_kernel<<<DD * DD / 4 / 256, 256>>>(Wk, wkH, wkL);
    split_kernel<<<DD * DD / 4 / 256, 256>>>(Wv, wvH, wvL);
    split_kernel<<<DD * DD / 4 / 256, 256>>>(Wo, woH, woL);

    // QKV projections
    {
        dim3 grid(DD / 128, MS / 128, 3);
        gemm_qkv_tc<<<grid, 256, SMEM_GEMM_SZ>>>(xH, xL);
    }

    // Fused RoPE + split (Q scaled), and V transpose + split
    {
        int total_pairs = MS * DD / 2;
        rope_split_kernel<<<total_pairs / 256, 256>>>(gQ, gK, tp);
        dim3 vgrid(SS / 64, BB * HH);
        vt_split_kernel<<<vgrid, 256>>>(gV);
    }

    // Causal flash attention (pre-split, cp.async pipelined)
    {
        dim3 agrid(SS / 128, BB * HH);
        attn_mma_kernel<<<agrid, 256>>>(qH, qL, kHp, kLp, vtH, vtL, aoH, aoL);
    }

    // Output projection
    {
        dim3 grid(DD / 128, MS / 128);
        gemm_out_tc<<<grid, 256, SMEM_GEMM_SZ>>>(aoH, aoL, out);
    }
}